// round 13
// baseline (speedup 1.0000x reference)
#include <cuda_runtime.h>
#include <cuda_bf16.h>
#include <cstdint>
#include <math.h>

// Problem constants
#define Bz   4
#define SQL  2048
#define SKL  2048
#define Dm   1024
#define Hh   16
#define DHd  64
#define NR   (Bz*SQL)          // 8192 rows
#define GK   3072              // split-bf16 K' = 3*1024
#define NCHUNK 48              // GK / 64
#define HD2  192               // split head dim 3*64

// -------- scratch (device globals; no allocation allowed) --------
__device__ float g_qp [NR*Dm];
__device__ float g_att[NR*Dm];
__device__ float g_x  [NR*Dm];
__device__ float g_y  [NR*Dm];
__device__ __nv_bfloat16 g_a2q[(size_t)NR*GK];
__device__ __nv_bfloat16 g_a2k[(size_t)NR*GK];
__device__ __nv_bfloat16 g_a2v[(size_t)NR*GK];
__device__ __nv_bfloat16 g_w2q[(size_t)Dm*GK];
__device__ __nv_bfloat16 g_w2k[(size_t)Dm*GK];
__device__ __nv_bfloat16 g_w2v[(size_t)Dm*GK];
__device__ __nv_bfloat16 g_w2o[(size_t)Dm*GK];
__device__ __nv_bfloat16 g_q2x[(size_t)Bz*Hh*SQL*HD2];
__device__ __nv_bfloat16 g_k2x[(size_t)Bz*Hh*SKL*HD2];
__device__ __nv_bfloat16 g_v2x[(size_t)Bz*Hh*SKL*DHd];
__device__ float g_mf [Bz*SKL];

// ============================================================================
// helpers
// ============================================================================
__device__ __forceinline__ uint32_t smem_u32(const void* p) {
    uint32_t a;
    asm("{ .reg .u64 t; cvta.to.shared.u64 t, %1; cvt.u32.u64 %0, t; }"
        : "=r"(a) : "l"(p));
    return a;
}
#define CP_ASYNC16(saddr, gptr) \
    asm volatile("cp.async.cg.shared.global [%0], [%1], 16;" \
                 :: "r"(saddr), "l"(gptr))
#define CP_COMMIT() asm volatile("cp.async.commit_group;" ::: "memory")
#define CP_WAIT1()  asm volatile("cp.async.wait_group 1;" ::: "memory")
#define CP_WAIT0()  asm volatile("cp.async.wait_group 0;" ::: "memory")

#define LDMX4(r0,r1,r2,r3,addr) \
    asm volatile("ldmatrix.sync.aligned.m8n8.x4.shared.b16 {%0,%1,%2,%3}, [%4];" \
                 : "=r"(r0), "=r"(r1), "=r"(r2), "=r"(r3) : "r"(addr))
#define LDMX4T(r0,r1,r2,r3,addr) \
    asm volatile("ldmatrix.sync.aligned.m8n8.x4.trans.shared.b16 {%0,%1,%2,%3}, [%4];" \
                 : "=r"(r0), "=r"(r1), "=r"(r2), "=r"(r3) : "r"(addr))

#define MMA16816(d, a, b) \
    asm volatile("mma.sync.aligned.m16n8k16.row.col.f32.bf16.bf16.f32 " \
                 "{%0,%1,%2,%3}, {%4,%5,%6,%7}, {%8,%9}, {%0,%1,%2,%3};" \
                 : "+f"((d)[0]), "+f"((d)[1]), "+f"((d)[2]), "+f"((d)[3]) \
                 : "r"((a)[0]), "r"((a)[1]), "r"((a)[2]), "r"((a)[3]), \
                   "r"((b)[0]), "r"((b)[1]))

__device__ __forceinline__ uint32_t packbf(float a, float b) {
    __nv_bfloat162 t = __floats2bfloat162_rn(a, b);
    return *(uint32_t*)&t;
}
__device__ __forceinline__ void split1(float v, __nv_bfloat16& hi, __nv_bfloat16& lo) {
    hi = __float2bfloat16(v);
    lo = __float2bfloat16(v - __bfloat162float(hi));
}
__device__ __forceinline__ uint32_t pack2(__nv_bfloat16 a, __nv_bfloat16 b) {
    return (uint32_t)(*(uint16_t*)&a) | ((uint32_t)(*(uint16_t*)&b) << 16);
}

// ============================================================================
// conversion kernels
// ============================================================================
__global__ __launch_bounds__(256) void conv_a3(
    const float* __restrict__ q, const float* __restrict__ k,
    const float* __restrict__ v,
    __nv_bfloat16* __restrict__ aq, __nv_bfloat16* __restrict__ ak,
    __nv_bfloat16* __restrict__ av)
{
    int z = blockIdx.z;
    const float* A = (z == 0) ? q : (z == 1) ? k : v;
    __nv_bfloat16* A2 = (z == 0) ? aq : (z == 1) ? ak : av;
    size_t i4 = (size_t)blockIdx.x * 256 + threadIdx.x;
    size_t e  = i4 * 4;
    int row = (int)(e >> 10);
    int kk  = (int)(e & 1023);
    float4 vv = *(const float4*)(A + e);
    __nv_bfloat16 h0, l0, h1, l1, h2, l2, h3, l3;
    split1(vv.x, h0, l0); split1(vv.y, h1, l1);
    split1(vv.z, h2, l2); split1(vv.w, h3, l3);
    uint2 hp = make_uint2(pack2(h0, h1), pack2(h2, h3));
    uint2 lp = make_uint2(pack2(l0, l1), pack2(l2, l3));
    size_t base = (size_t)row * GK + kk;
    *(uint2*)(A2 + base)        = hp;
    *(uint2*)(A2 + base + 1024) = lp;
    *(uint2*)(A2 + base + 2048) = hp;
}

__global__ __launch_bounds__(256) void conv_w4(
    const float* __restrict__ Wq, const float* __restrict__ Wk,
    const float* __restrict__ Wv, const float* __restrict__ Wo,
    __nv_bfloat16* __restrict__ Tq, __nv_bfloat16* __restrict__ Tk,
    __nv_bfloat16* __restrict__ Tv, __nv_bfloat16* __restrict__ To)
{
    int z = blockIdx.z;
    const float* W = (z == 0) ? Wq : (z == 1) ? Wk : (z == 2) ? Wv : Wo;
    __nv_bfloat16* Wt = (z == 0) ? Tq : (z == 1) ? Tk : (z == 2) ? Tv : To;
    __shared__ float t[32][33];
    int tx = threadIdx.x, ty = threadIdx.y;
    int n0 = blockIdx.x * 32, k0 = blockIdx.y * 32;
#pragma unroll
    for (int i = 0; i < 4; i++)
        t[ty * 4 + i][tx] = W[(size_t)(k0 + ty * 4 + i) * Dm + n0 + tx];
    __syncthreads();
#pragma unroll
    for (int i = 0; i < 4; i++) {
        int n = ty * 4 + i;
        __nv_bfloat16 hi, lo;
        split1(t[tx][n], hi, lo);
        size_t base = (size_t)(n0 + n) * GK;
        Wt[base + k0 + tx]        = hi;
        Wt[base + 1024 + k0 + tx] = hi;
        Wt[base + 2048 + k0 + tx] = lo;
    }
}

__global__ __launch_bounds__(256) void conv_mask(
    const int* __restrict__ m, float* __restrict__ mf)
{
    int i = blockIdx.x * 256 + threadIdx.x;
    if (i < Bz * SKL) mf[i] = m[i] ? 1.0f : 0.0f;
}

// ============================================================================
// GEMM core: 128x128 tile, 3-stage cp.async, reg-double-buffered fragments
// ============================================================================
#define SST   144
#define MATB  (128 * SST)
#define STAGEB (2 * MATB)          // 36864
#define GEMM_SMEM (3 * STAGEB)     // 110592

__device__ __forceinline__ void gemm_core(
    const char* gA, const char* gB, uint32_t sb, int tid,
    int warp_m, int warp_n, int lane, float acc[4][4][4])
{
    int lrow[4], lcol[4];
#pragma unroll
    for (int it = 0; it < 4; it++) {
        int f = tid + it * 256;
        lrow[it] = f >> 3;
        lcol[it] = (f & 7) * 16;
    }
#pragma unroll
    for (int mt = 0; mt < 4; mt++)
#pragma unroll
        for (int nt = 0; nt < 4; nt++)
#pragma unroll
            for (int r = 0; r < 4; r++) acc[mt][nt][r] = 0.f;

#pragma unroll
    for (int p = 0; p < 2; p++) {
        uint32_t as = sb + p * STAGEB, bs = as + MATB;
#pragma unroll
        for (int it = 0; it < 4; it++) {
            long go = (long)lrow[it] * (GK * 2) + p * 128 + lcol[it];
            uint32_t so = (uint32_t)(lrow[it] * SST + lcol[it]);
            CP_ASYNC16(as + so, gA + go);
            CP_ASYNC16(bs + so, gB + go);
        }
        CP_COMMIT();
    }

    int arow = warp_m * 64 + (lane & 15);
    int acol = ((lane >> 4) << 3);
    int brow = warp_n * 32 + (lane & 7) + ((lane >> 4) << 3);
    int bcol = (((lane >> 3) & 1) << 3);

    for (int c = 0; c < NCHUNK; c++) {
        if (c < NCHUNK - 1) { CP_WAIT1(); } else { CP_WAIT0(); }
        __syncthreads();
        if (c + 2 < NCHUNK) {
            uint32_t as = sb + ((c + 2) % 3) * STAGEB, bs = as + MATB;
#pragma unroll
            for (int it = 0; it < 4; it++) {
                long go = (long)lrow[it] * (GK * 2) + (c + 2) * 128 + lcol[it];
                uint32_t so = (uint32_t)(lrow[it] * SST + lcol[it]);
                CP_ASYNC16(as + so, gA + go);
                CP_ASYNC16(bs + so, gB + go);
            }
            CP_COMMIT();
        }

        uint32_t aS = sb + (c % 3) * STAGEB;
        uint32_t bS = aS + MATB;

        // register double-buffered fragment pipeline over ks
        uint32_t abuf[2][4][4];
        uint32_t bbuf[2][4][2];
#pragma unroll
        for (int mt = 0; mt < 4; mt++) {
            uint32_t ad = aS + (uint32_t)((arow + mt * 16) * SST + acol * 2);
            LDMX4(abuf[0][mt][0], abuf[0][mt][1], abuf[0][mt][2], abuf[0][mt][3], ad);
        }
#pragma unroll
        for (int nh = 0; nh < 2; nh++) {
            uint32_t bd = bS + (uint32_t)((brow + nh * 16) * SST + bcol * 2);
            LDMX4(bbuf[0][nh * 2][0], bbuf[0][nh * 2][1],
                  bbuf[0][nh * 2 + 1][0], bbuf[0][nh * 2 + 1][1], bd);
        }

#pragma unroll
        for (int ks = 0; ks < 4; ks++) {
            int cb = ks & 1, nb = cb ^ 1;
            if (ks < 3) {
#pragma unroll
                for (int mt = 0; mt < 4; mt++) {
                    uint32_t ad = aS + (uint32_t)((arow + mt * 16) * SST
                                                  + ((ks + 1) * 16 + acol) * 2);
                    LDMX4(abuf[nb][mt][0], abuf[nb][mt][1],
                          abuf[nb][mt][2], abuf[nb][mt][3], ad);
                }
#pragma unroll
                for (int nh = 0; nh < 2; nh++) {
                    uint32_t bd = bS + (uint32_t)((brow + nh * 16) * SST
                                                  + ((ks + 1) * 16 + bcol) * 2);
                    LDMX4(bbuf[nb][nh * 2][0], bbuf[nb][nh * 2][1],
                          bbuf[nb][nh * 2 + 1][0], bbuf[nb][nh * 2 + 1][1], bd);
                }
            }
#pragma unroll
            for (int mt = 0; mt < 4; mt++)
#pragma unroll
                for (int nt = 0; nt < 4; nt++)
                    MMA16816(acc[mt][nt], abuf[cb][mt], bbuf[cb][nt]);
        }
    }
}

// Batched QKV projection GEMM
__global__ __launch_bounds__(256) void gemm_qkv(
    const __nv_bfloat16* __restrict__ aq, const __nv_bfloat16* __restrict__ ak,
    const __nv_bfloat16* __restrict__ av,
    const __nv_bfloat16* __restrict__ wq, const __nv_bfloat16* __restrict__ wk,
    const __nv_bfloat16* __restrict__ wv,
    const float* __restrict__ bq, const float* __restrict__ bk,
    const float* __restrict__ bv,
    float* __restrict__ qp, __nv_bfloat16* __restrict__ q2,
    __nv_bfloat16* __restrict__ k2, __nv_bfloat16* __restrict__ v2)
{
    extern __shared__ char smem[];
    uint32_t sb = smem_u32(smem);
    int tid  = threadIdx.x;
    int wid  = tid >> 5;
    int lane = tid & 31;
    int bx = blockIdx.x, by = blockIdx.y, z = blockIdx.z;
    int warp_m = wid >> 2, warp_n = wid & 3;

    const __nv_bfloat16* A2 = (z == 0) ? aq : (z == 1) ? ak : av;
    const __nv_bfloat16* B2 = (z == 0) ? wq : (z == 1) ? wk : wv;
    const float* bias       = (z == 0) ? bq : (z == 1) ? bk : bv;

    float acc[4][4][4];
    gemm_core((const char*)(A2 + (size_t)(by * 128) * GK),
              (const char*)(B2 + (size_t)(bx * 128) * GK),
              sb, tid, warp_m, warp_n, lane, acc);

    int g  = lane >> 2;
    int tg = lane & 3;
#pragma unroll
    for (int mt = 0; mt < 4; mt++) {
        int row0 = by * 128 + warp_m * 64 + mt * 16 + g;
#pragma unroll
        for (int nt = 0; nt < 4; nt++) {
            int col = bx * 128 + warp_n * 32 + nt * 8 + tg * 2;
            float2 bv2 = *(const float2*)(bias + col);
            int h = col >> 6, d = col & 63;
#pragma unroll
            for (int half = 0; half < 2; half++) {
                int row = row0 + half * 8;
                float v0 = acc[mt][nt][2 * half]     + bv2.x;
                float v1 = acc[mt][nt][2 * half + 1] + bv2.y;
                int bb = row >> 11, r = row & 2047;
                size_t hb = (size_t)((bb * 16 + h) * 2048 + r);
                __nv_bfloat16 h0, l0, h1, l1;
                split1(v0, h0, l0);
                split1(v1, h1, l1);
                uint32_t hp = pack2(h0, h1);
                uint32_t lp = pack2(l0, l1);
                if (z == 0) {
                    float2 o = {v0, v1};
                    *(float2*)(qp + (size_t)row * Dm + col) = o;
                    size_t base = hb * HD2;
                    *(uint32_t*)(q2 + base + d)       = hp;
                    *(uint32_t*)(q2 + base + 64 + d)  = lp;
                    *(uint32_t*)(q2 + base + 128 + d) = hp;
                } else if (z == 1) {
                    size_t base = hb * HD2;
                    *(uint32_t*)(k2 + base + d)       = hp;
                    *(uint32_t*)(k2 + base + 64 + d)  = hp;
                    *(uint32_t*)(k2 + base + 128 + d) = lp;
                } else {
                    *(uint32_t*)(v2 + hb * DHd + d) = hp;
                }
            }
        }
    }
}

// Output projection GEMM
__global__ __launch_bounds__(256) void gemm_o(
    const __nv_bfloat16* __restrict__ A2, const __nv_bfloat16* __restrict__ B2,
    const float* __restrict__ bias, float* __restrict__ C)
{
    extern __shared__ char smem[];
    uint32_t sb = smem_u32(smem);
    int tid  = threadIdx.x;
    int wid  = tid >> 5;
    int lane = tid & 31;
    int bx = blockIdx.x, by = blockIdx.y;
    int warp_m = wid >> 2, warp_n = wid & 3;

    float acc[4][4][4];
    gemm_core((const char*)(A2 + (size_t)(by * 128) * GK),
              (const char*)(B2 + (size_t)(bx * 128) * GK),
              sb, tid, warp_m, warp_n, lane, acc);

    int g  = lane >> 2;
    int tg = lane & 3;
#pragma unroll
    for (int mt = 0; mt < 4; mt++) {
        int row = by * 128 + warp_m * 64 + mt * 16 + g;
#pragma unroll
        for (int nt = 0; nt < 4; nt++) {
            int col = bx * 128 + warp_n * 32 + nt * 8 + tg * 2;
            float2 bv = *(const float2*)(bias + col);
            float2 o0 = {acc[mt][nt][0] + bv.x, acc[mt][nt][1] + bv.y};
            float2 o1 = {acc[mt][nt][2] + bv.x, acc[mt][nt][3] + bv.y};
            *(float2*)(C + (size_t)row * Dm + col)       = o0;
            *(float2*)(C + (size_t)(row + 8) * Dm + col) = o1;
        }
    }
}

// ============================================================================
// Flash attention, mma.sync bf16; 3-stage ring, reg-pipelined fragments
// ============================================================================
#define QROWB 400
#define VROWB 144
#define KTILEB (64 * QROWB)
#define VOFF   KTILEB
#define MOFF   (KTILEB + 64 * VROWB)
#define STGB   (MOFF + 256)        // 35072
#define FLASH_SMEM (3 * STGB)      // 105216

__device__ __forceinline__ void flash_prefetch(
    uint32_t ds, const char* gK, const char* gV, const char* gM,
    int kt, int tid)
{
    const char* nK = gK + (long)kt * 64 * (HD2 * 2);
    const char* nV = gV + (long)kt * 64 * 128;
#pragma unroll
    for (int it = 0; it < 6; it++) {
        int f = tid + it * 256;
        int r = f / 24, c = f % 24;
        CP_ASYNC16(ds + r * QROWB + c * 16, nK + (long)r * (HD2 * 2) + c * 16);
    }
#pragma unroll
    for (int it = 0; it < 2; it++) {
        int f = tid + it * 256;
        int r = f >> 3, c = f & 7;
        CP_ASYNC16(ds + VOFF + r * VROWB + c * 16, nV + (long)r * 128 + c * 16);
    }
    if (tid < 16) CP_ASYNC16(ds + MOFF + tid * 16, gM + kt * 256 + tid * 16);
    CP_COMMIT();
}

__global__ __launch_bounds__(256, 1) void flash_mma(
    const __nv_bfloat16* __restrict__ Q2, const __nv_bfloat16* __restrict__ K2,
    const __nv_bfloat16* __restrict__ V2, const float* __restrict__ MF,
    float* __restrict__ attn)
{
    extern __shared__ char smem[];
    uint32_t sb = smem_u32(smem);
    int tid  = threadIdx.x;
    int wid  = tid >> 5;
    int lane = tid & 31;
    int qx = blockIdx.x, h = blockIdx.y, b = blockIdx.z;

    size_t bh = (size_t)(b * 16 + h) * 2048;
    const char* gQ = (const char*)(Q2 + (bh + qx * 128) * HD2);
    const char* gK = (const char*)(K2 + bh * HD2);
    const char* gV = (const char*)(V2 + bh * DHd);
    const char* gM = (const char*)(MF + b * SKL);

#pragma unroll
    for (int it = 0; it < 12; it++) {
        int f = tid + it * 256;
        int r = f / 24, c = f % 24;
        CP_ASYNC16(sb + r * QROWB + c * 16, gQ + (long)r * (HD2 * 2) + c * 16);
    }
    CP_COMMIT();
    CP_WAIT0();
    __syncthreads();

    uint32_t qf[12][4];
    {
        int arow = wid * 16 + (lane & 15);
        int acol = ((lane >> 4) << 3);
#pragma unroll
        for (int ks = 0; ks < 12; ks++)
            LDMX4(qf[ks][0], qf[ks][1], qf[ks][2], qf[ks][3],
                  sb + arow * QROWB + (ks * 16 + acol) * 2);
    }
    __syncthreads();

    int g  = lane >> 2;
    int tg = lane & 3;

    float O[8][4];
#pragma unroll
    for (int dt = 0; dt < 8; dt++)
#pragma unroll
        for (int r = 0; r < 4; r++) O[dt][r] = 0.f;
    float m0 = -30000.f, m1 = -30000.f, l0 = 0.f, l1 = 0.f;

    const float scale = 0.03125f;

    flash_prefetch(sb,        gK, gV, gM, 0, tid);
    flash_prefetch(sb + STGB, gK, gV, gM, 1, tid);

    int brow = (lane & 7) + ((lane >> 4) << 3);
    int bcol = (((lane >> 3) & 1) << 3);
    int vrow = (lane & 7) + (((lane >> 3) & 1) << 3);
    int vcol = ((lane >> 4) << 3);

    for (int kt = 0; kt < 32; kt++) {
        if (kt < 31) { CP_WAIT1(); } else { CP_WAIT0(); }
        __syncthreads();
        if (kt + 2 < 32)
            flash_prefetch(sb + ((kt + 2) % 3) * STGB, gK, gV, gM, kt + 2, tid);

        uint32_t kS = sb + (kt % 3) * STGB;
        uint32_t vS = kS + VOFF;
        uint32_t mS = kS + MOFF;

        // ---- S = Q' K'^T, register-pipelined over flattened (ks, j) ----
        float s[8][4];
#pragma unroll
        for (int nt = 0; nt < 8; nt++)
#pragma unroll
            for (int r = 0; r < 4; r++) s[nt][r] = 0.f;

        uint32_t kb[2][2][2];
        LDMX4(kb[0][0][0], kb[0][0][1], kb[0][1][0], kb[0][1][1],
              kS + (uint32_t)(brow * QROWB + bcol * 2));
#pragma unroll
        for (int idx = 0; idx < 48; idx++) {
            int ks = idx >> 2, j = idx & 3;
            int cb = idx & 1, nb = cb ^ 1;
            if (idx < 47) {
                int ks2 = (idx + 1) >> 2, j2 = (idx + 1) & 3;
                LDMX4(kb[nb][0][0], kb[nb][0][1], kb[nb][1][0], kb[nb][1][1],
                      kS + (uint32_t)((j2 * 16 + brow) * QROWB
                                      + (ks2 * 16 + bcol) * 2));
            }
            MMA16816(s[2 * j],     qf[ks], kb[cb][0]);
            MMA16816(s[2 * j + 1], qf[ks], kb[cb][1]);
        }

        // ---- softmax (online) ----
        float mf[8][2];
#pragma unroll
        for (int nt = 0; nt < 8; nt++) {
            mf[nt][0] = *(const float*)((const char*)smem + (mS - sb) + (nt * 8 + 2 * tg) * 4);
            mf[nt][1] = *(const float*)((const char*)smem + (mS - sb) + (nt * 8 + 2 * tg + 1) * 4);
        }
        float rm0 = -30000.f, rm1 = -30000.f;
#pragma unroll
        for (int nt = 0; nt < 8; nt++) {
#pragma unroll
            for (int e = 0; e < 2; e++) {
                float off = (mf[nt][e] - 1.0f) * 30000.f;
                s[nt][e]     = s[nt][e]     * scale + off;
                s[nt][2 + e] = s[nt][2 + e] * scale + off;
                rm0 = fmaxf(rm0, s[nt][e]);
                rm1 = fmaxf(rm1, s[nt][2 + e]);
            }
        }
        rm0 = fmaxf(rm0, __shfl_xor_sync(0xffffffffu, rm0, 1));
        rm0 = fmaxf(rm0, __shfl_xor_sync(0xffffffffu, rm0, 2));
        rm1 = fmaxf(rm1, __shfl_xor_sync(0xffffffffu, rm1, 1));
        rm1 = fmaxf(rm1, __shfl_xor_sync(0xffffffffu, rm1, 2));

        float mn0 = fmaxf(m0, rm0), mn1 = fmaxf(m1, rm1);
        float al0 = __expf(m0 - mn0), al1 = __expf(m1 - mn1);
        m0 = mn0; m1 = mn1;

        float rs0 = 0.f, rs1 = 0.f;
#pragma unroll
        for (int nt = 0; nt < 8; nt++) {
#pragma unroll
            for (int e = 0; e < 2; e++) {
                float p0 = __expf(s[nt][e]     - mn0) * mf[nt][e];
                float p1 = __expf(s[nt][2 + e] - mn1) * mf[nt][e];
                s[nt][e] = p0;  s[nt][2 + e] = p1;
                rs0 += p0;  rs1 += p1;
            }
        }
        rs0 += __shfl_xor_sync(0xffffffffu, rs0, 1);
        rs0 += __shfl_xor_sync(0xffffffffu, rs0, 2);
        rs1 += __shfl_xor_sync(0xffffffffu, rs1, 1);
        rs1 += __shfl_xor_sync(0xffffffffu, rs1, 2);
        l0 = l0 * al0 + rs0;
        l1 = l1 * al1 + rs1;

#pragma unroll
        for (int dt = 0; dt < 8; dt++) {
            O[dt][0] *= al0; O[dt][1] *= al0;
            O[dt][2] *= al1; O[dt][3] *= al1;
        }

        // ---- O += P V, register-pipelined over flattened (ks, j) ----
        uint32_t pa[4][4];
#pragma unroll
        for (int ks = 0; ks < 4; ks++) {
            pa[ks][0] = packbf(s[2 * ks][0],     s[2 * ks][1]);
            pa[ks][1] = packbf(s[2 * ks][2],     s[2 * ks][3]);
            pa[ks][2] = packbf(s[2 * ks + 1][0], s[2 * ks + 1][1]);
            pa[ks][3] = packbf(s[2 * ks + 1][2], s[2 * ks + 1][3]);
        }
        uint32_t vb[2][2][2];
        LDMX4T(vb[0][0][0], vb[0][0][1], vb[0][1][0], vb[0][1][1],
               vS + (uint32_t)(vrow * VROWB + vcol * 2));
#pragma unroll
        for (int idx = 0; idx < 16; idx++) {
            int ks = idx >> 2, j = idx & 3;
            int cb = idx & 1, nb = cb ^ 1;
            if (idx < 15) {
                int ks2 = (idx + 1) >> 2, j2 = (idx + 1) & 3;
                LDMX4T(vb[nb][0][0], vb[nb][0][1], vb[nb][1][0], vb[nb][1][1],
                       vS + (uint32_t)((ks2 * 16 + vrow) * VROWB
                                       + (j2 * 16 + vcol) * 2));
            }
            MMA16816(O[2 * j],     pa[ks], vb[cb][0]);
            MMA16816(O[2 * j + 1], pa[ks], vb[cb][1]);
        }
    }

    float inv0 = l0 > 0.f ? 1.f / l0 : 0.f;
    float inv1 = l1 > 0.f ? 1.f / l1 : 0.f;
    int row0 = qx * 128 + wid * 16 + g;
    float* oBase = attn + (size_t)(b * SQL) * Dm + h * DHd;
#pragma unroll
    for (int dt = 0; dt < 8; dt++) {
        int col = dt * 8 + 2 * tg;
        float2 o0 = {O[dt][0] * inv0, O[dt][1] * inv0};
        float2 o1 = {O[dt][2] * inv1, O[dt][3] * inv1};
        *(float2*)(oBase + (size_t)row0 * Dm + col)       = o0;
        *(float2*)(oBase + (size_t)(row0 + 8) * Dm + col) = o1;
    }
}

// ============================================================================
// out = LayerNorm(X + (relu? relu(Y) : Y)) * g + beta; optional split output
// ============================================================================
__global__ __launch_bounds__(256) void add_ln(
    const float* __restrict__ X, const float* __restrict__ Y,
    const float* __restrict__ g, const float* __restrict__ be,
    float* __restrict__ out, __nv_bfloat16* __restrict__ a2, int dorelu)
{
    int row = blockIdx.x;
    int tid = threadIdx.x;
    size_t base = (size_t)row * Dm + tid * 4;

    float4 x4 = *(const float4*)(X + base);
    float4 y4 = *(const float4*)(Y + base);
    if (dorelu) {
        y4.x = fmaxf(y4.x, 0.f); y4.y = fmaxf(y4.y, 0.f);
        y4.z = fmaxf(y4.z, 0.f); y4.w = fmaxf(y4.w, 0.f);
    }
    float v[4] = {x4.x + y4.x, x4.y + y4.y, x4.z + y4.z, x4.w + y4.w};

    float s  = v[0] + v[1] + v[2] + v[3];
    float sq = v[0]*v[0] + v[1]*v[1] + v[2]*v[2] + v[3]*v[3];
#pragma unroll
    for (int off = 16; off > 0; off >>= 1) {
        s  += __shfl_xor_sync(0xffffffffu, s,  off);
        sq += __shfl_xor_sync(0xffffffffu, sq, off);
    }
    __shared__ float sh[16];
    int w = tid >> 5;
    if ((tid & 31) == 0) { sh[w] = s; sh[8 + w] = sq; }
    __syncthreads();
    s = 0.f; sq = 0.f;
#pragma unroll
    for (int i = 0; i < 8; i++) { s += sh[i]; sq += sh[8 + i]; }

    float mean = s * (1.f / 1024.f);
    float var  = fmaf(-mean, mean, sq * (1.f / 1024.f));
    float rstd = rsqrtf(var + 1e-6f);

    float4 g4 = *(const float4*)(g  + tid * 4);
    float4 b4 = *(const float4*)(be + tid * 4);
    float o[4];
    o[0] = (v[0] - mean) * rstd * g4.x + b4.x;
    o[1] = (v[1] - mean) * rstd * g4.y + b4.y;
    o[2] = (v[2] - mean) * rstd * g4.z + b4.z;
    o[3] = (v[3] - mean) * rstd * g4.w + b4.w;
    *(float4*)(out + base) = *(float4*)o;

    if (a2) {
        size_t ab = (size_t)row * GK + tid * 4;
        __nv_bfloat16 h0, l0, h1, l1, h2, l2, h3, l3;
        split1(o[0], h0, l0); split1(o[1], h1, l1);
        split1(o[2], h2, l2); split1(o[3], h3, l3);
        uint2 hp = make_uint2(pack2(h0, h1), pack2(h2, h3));
        uint2 lp = make_uint2(pack2(l0, l1), pack2(l2, l3));
        *(uint2*)(a2 + ab)        = hp;
        *(uint2*)(a2 + ab + 1024) = lp;
        *(uint2*)(a2 + ab + 2048) = hp;
    }
}

// ============================================================================
extern "C" void kernel_launch(void* const* d_in, const int* in_sizes, int n_in,
                              void* d_out, int out_size)
{
    const float* q    = (const float*)d_in[0];
    const float* k    = (const float*)d_in[1];
    const float* v    = (const float*)d_in[2];
    const int*   mask = (const int*)d_in[3];
    const float* Wq   = (const float*)d_in[4];
    const float* bq   = (const float*)d_in[5];
    const float* Wk   = (const float*)d_in[6];
    const float* bk   = (const float*)d_in[7];
    const float* Wv   = (const float*)d_in[8];
    const float* bv   = (const float*)d_in[9];
    const float* Wo   = (const float*)d_in[10];
    const float* bo   = (const float*)d_in[11];
    const float* g1   = (const float*)d_in[12];
    const float* b1   = (const float*)d_in[13];
    const float* g2   = (const float*)d_in[14];
    const float* b2   = (const float*)d_in[15];

    float *qp, *at, *x, *y, *mf;
    __nv_bfloat16 *aq, *ak, *av, *w2q, *w2k, *w2v, *w2o, *q2, *k2, *v2;
    cudaGetSymbolAddress((void**)&qp, g_qp);
    cudaGetSymbolAddress((void**)&at, g_att);
    cudaGetSymbolAddress((void**)&x,  g_x);
    cudaGetSymbolAddress((void**)&y,  g_y);
    cudaGetSymbolAddress((void**)&aq,  g_a2q);
    cudaGetSymbolAddress((void**)&ak,  g_a2k);
    cudaGetSymbolAddress((void**)&av,  g_a2v);
    cudaGetSymbolAddress((void**)&w2q, g_w2q);
    cudaGetSymbolAddress((void**)&w2k, g_w2k);
    cudaGetSymbolAddress((void**)&w2v, g_w2v);
    cudaGetSymbolAddress((void**)&w2o, g_w2o);
    cudaGetSymbolAddress((void**)&q2,  g_q2x);
    cudaGetSymbolAddress((void**)&k2,  g_k2x);
    cudaGetSymbolAddress((void**)&v2,  g_v2x);
    cudaGetSymbolAddress((void**)&mf,  g_mf);

    cudaFuncSetAttribute(gemm_qkv, cudaFuncAttributeMaxDynamicSharedMemorySize,
                         GEMM_SMEM);
    cudaFuncSetAttribute(gemm_o, cudaFuncAttributeMaxDynamicSharedMemorySize,
                         GEMM_SMEM);
    cudaFuncSetAttribute(flash_mma, cudaFuncAttributeMaxDynamicSharedMemorySize,
                         FLASH_SMEM);

    conv_w4<<<dim3(Dm / 32, Dm / 32, 4), dim3(32, 8)>>>(
        Wq, Wk, Wv, Wo, w2q, w2k, w2v, w2o);

    int cab4 = (int)(((size_t)NR * Dm) / 1024);
    conv_a3<<<dim3(cab4, 1, 3), 256>>>(q, k, v, aq, ak, av);
    conv_mask<<<(Bz * SKL + 255) / 256, 256>>>(mask, mf);

    gemm_qkv<<<dim3(Dm / 128, NR / 128, 3), 256, GEMM_SMEM>>>(
        aq, ak, av, w2q, w2k, w2v, bq, bk, bv, qp, q2, k2, v2);

    flash_mma<<<dim3(SQL / 128, Hh, Bz), 256, FLASH_SMEM>>>(q2, k2, v2, mf, at);

    add_ln<<<NR, 256>>>(qp, at, g1, b1, x, aq, 0);

    gemm_o<<<dim3(Dm / 128, NR / 128), 256, GEMM_SMEM>>>(aq, w2o, bo, y);

    add_ln<<<NR, 256>>>(x, y, g2, b2, (float*)d_out, (__nv_bfloat16*)0, 1);
}

// round 14
// speedup vs baseline: 1.0037x; 1.0037x over previous
#include <cuda_runtime.h>
#include <cuda_bf16.h>
#include <cstdint>
#include <math.h>

// Problem constants
#define Bz   4
#define SQL  2048
#define SKL  2048
#define Dm   1024
#define Hh   16
#define DHd  64
#define NR   (Bz*SQL)          // 8192 rows
#define GK   3072              // split-bf16 K' = 3*1024 (projection GEMMs)
#define NCHUNK 48              // GK / 64
#define HD2F 128               // flash split head dim 2*64

// -------- scratch (device globals; no allocation allowed) --------
__device__ float g_qp [NR*Dm];
__device__ float g_att[NR*Dm];
__device__ float g_x  [NR*Dm];
__device__ float g_y  [NR*Dm];
__device__ __nv_bfloat16 g_a2q[(size_t)NR*GK];
__device__ __nv_bfloat16 g_a2k[(size_t)NR*GK];
__device__ __nv_bfloat16 g_a2v[(size_t)NR*GK];
__device__ __nv_bfloat16 g_w2q[(size_t)Dm*GK];
__device__ __nv_bfloat16 g_w2k[(size_t)Dm*GK];
__device__ __nv_bfloat16 g_w2v[(size_t)Dm*GK];
__device__ __nv_bfloat16 g_w2o[(size_t)Dm*GK];
__device__ __nv_bfloat16 g_q2x[(size_t)Bz*Hh*SQL*HD2F];
__device__ __nv_bfloat16 g_k2x[(size_t)Bz*Hh*SKL*HD2F];
__device__ __nv_bfloat16 g_v2x[(size_t)Bz*Hh*SKL*DHd];
__device__ float g_mf [Bz*SKL];

// ============================================================================
// helpers
// ============================================================================
__device__ __forceinline__ uint32_t smem_u32(const void* p) {
    uint32_t a;
    asm("{ .reg .u64 t; cvta.to.shared.u64 t, %1; cvt.u32.u64 %0, t; }"
        : "=r"(a) : "l"(p));
    return a;
}
#define CP_ASYNC16(saddr, gptr) \
    asm volatile("cp.async.cg.shared.global [%0], [%1], 16;" \
                 :: "r"(saddr), "l"(gptr))
#define CP_COMMIT() asm volatile("cp.async.commit_group;" ::: "memory")
#define CP_WAIT1()  asm volatile("cp.async.wait_group 1;" ::: "memory")
#define CP_WAIT0()  asm volatile("cp.async.wait_group 0;" ::: "memory")

#define LDMX4(r0,r1,r2,r3,addr) \
    asm volatile("ldmatrix.sync.aligned.m8n8.x4.shared.b16 {%0,%1,%2,%3}, [%4];" \
                 : "=r"(r0), "=r"(r1), "=r"(r2), "=r"(r3) : "r"(addr))
#define LDMX4T(r0,r1,r2,r3,addr) \
    asm volatile("ldmatrix.sync.aligned.m8n8.x4.trans.shared.b16 {%0,%1,%2,%3}, [%4];" \
                 : "=r"(r0), "=r"(r1), "=r"(r2), "=r"(r3) : "r"(addr))

#define MMA16816(d, a, b) \
    asm volatile("mma.sync.aligned.m16n8k16.row.col.f32.bf16.bf16.f32 " \
                 "{%0,%1,%2,%3}, {%4,%5,%6,%7}, {%8,%9}, {%0,%1,%2,%3};" \
                 : "+f"((d)[0]), "+f"((d)[1]), "+f"((d)[2]), "+f"((d)[3]) \
                 : "r"((a)[0]), "r"((a)[1]), "r"((a)[2]), "r"((a)[3]), \
                   "r"((b)[0]), "r"((b)[1]))

__device__ __forceinline__ uint32_t packbf(float a, float b) {
    __nv_bfloat162 t = __floats2bfloat162_rn(a, b);
    return *(uint32_t*)&t;
}
__device__ __forceinline__ void split1(float v, __nv_bfloat16& hi, __nv_bfloat16& lo) {
    hi = __float2bfloat16(v);
    lo = __float2bfloat16(v - __bfloat162float(hi));
}
__device__ __forceinline__ uint32_t pack2(__nv_bfloat16 a, __nv_bfloat16 b) {
    return (uint32_t)(*(uint16_t*)&a) | ((uint32_t)(*(uint16_t*)&b) << 16);
}

// ============================================================================
// conversion kernels
// ============================================================================
__global__ __launch_bounds__(256) void conv_a3(
    const float* __restrict__ q, const float* __restrict__ k,
    const float* __restrict__ v,
    __nv_bfloat16* __restrict__ aq, __nv_bfloat16* __restrict__ ak,
    __nv_bfloat16* __restrict__ av)
{
    int z = blockIdx.z;
    const float* A = (z == 0) ? q : (z == 1) ? k : v;
    __nv_bfloat16* A2 = (z == 0) ? aq : (z == 1) ? ak : av;
    size_t i4 = (size_t)blockIdx.x * 256 + threadIdx.x;
    size_t e  = i4 * 4;
    int row = (int)(e >> 10);
    int kk  = (int)(e & 1023);
    float4 vv = *(const float4*)(A + e);
    __nv_bfloat16 h0, l0, h1, l1, h2, l2, h3, l3;
    split1(vv.x, h0, l0); split1(vv.y, h1, l1);
    split1(vv.z, h2, l2); split1(vv.w, h3, l3);
    uint2 hp = make_uint2(pack2(h0, h1), pack2(h2, h3));
    uint2 lp = make_uint2(pack2(l0, l1), pack2(l2, l3));
    size_t base = (size_t)row * GK + kk;
    *(uint2*)(A2 + base)        = hp;
    *(uint2*)(A2 + base + 1024) = lp;
    *(uint2*)(A2 + base + 2048) = hp;
}

__global__ __launch_bounds__(256) void conv_w4(
    const float* __restrict__ Wq, const float* __restrict__ Wk,
    const float* __restrict__ Wv, const float* __restrict__ Wo,
    __nv_bfloat16* __restrict__ Tq, __nv_bfloat16* __restrict__ Tk,
    __nv_bfloat16* __restrict__ Tv, __nv_bfloat16* __restrict__ To)
{
    int z = blockIdx.z;
    const float* W = (z == 0) ? Wq : (z == 1) ? Wk : (z == 2) ? Wv : Wo;
    __nv_bfloat16* Wt = (z == 0) ? Tq : (z == 1) ? Tk : (z == 2) ? Tv : To;
    __shared__ float t[32][33];
    int tx = threadIdx.x, ty = threadIdx.y;
    int n0 = blockIdx.x * 32, k0 = blockIdx.y * 32;
#pragma unroll
    for (int i = 0; i < 4; i++)
        t[ty * 4 + i][tx] = W[(size_t)(k0 + ty * 4 + i) * Dm + n0 + tx];
    __syncthreads();
#pragma unroll
    for (int i = 0; i < 4; i++) {
        int n = ty * 4 + i;
        __nv_bfloat16 hi, lo;
        split1(t[tx][n], hi, lo);
        size_t base = (size_t)(n0 + n) * GK;
        Wt[base + k0 + tx]        = hi;
        Wt[base + 1024 + k0 + tx] = hi;
        Wt[base + 2048 + k0 + tx] = lo;
    }
}

__global__ __launch_bounds__(256) void conv_mask(
    const int* __restrict__ m, float* __restrict__ mf)
{
    int i = blockIdx.x * 256 + threadIdx.x;
    if (i < Bz * SKL) mf[i] = m[i] ? 1.0f : 0.0f;
}

// ============================================================================
// GEMM core: 128x256 CTA tile, 64x64 warp tile, 3-stage cp.async, 1 CTA/SM
// ============================================================================
#define SST   144
#define ASTB  (128 * SST)          // 18432
#define BSTB  (256 * SST)          // 36864
#define STG2  (ASTB + BSTB)        // 55296
#define GEMM_SMEM (3 * STG2)       // 165888

__device__ __forceinline__ void gemm_ld_chunk(
    const char* gA, const char* gB, uint32_t as, int tid, int c)
{
    uint32_t bs = as + ASTB;
#pragma unroll
    for (int it = 0; it < 4; it++) {          // A: 128 rows x 8 chunks16
        int f = tid + it * 256;
        int r = f >> 3, col = (f & 7) * 16;
        CP_ASYNC16(as + (uint32_t)(r * SST + col),
                   gA + (long)r * (GK * 2) + c * 128 + col);
    }
#pragma unroll
    for (int it = 0; it < 8; it++) {          // B: 256 rows x 8 chunks16
        int f = tid + it * 256;
        int r = f >> 3, col = (f & 7) * 16;
        CP_ASYNC16(bs + (uint32_t)(r * SST + col),
                   gB + (long)r * (GK * 2) + c * 128 + col);
    }
    CP_COMMIT();
}

__device__ __forceinline__ void gemm_core(
    const char* gA, const char* gB, uint32_t sb, int tid,
    int warp_m, int warp_n, int lane, float acc[4][8][4])
{
#pragma unroll
    for (int mt = 0; mt < 4; mt++)
#pragma unroll
        for (int nt = 0; nt < 8; nt++)
#pragma unroll
            for (int r = 0; r < 4; r++) acc[mt][nt][r] = 0.f;

    gemm_ld_chunk(gA, gB, sb, tid, 0);
    gemm_ld_chunk(gA, gB, sb + STG2, tid, 1);

    int arow = warp_m * 64 + (lane & 15);
    int acol = ((lane >> 4) << 3);
    int brow = warp_n * 64 + (lane & 7) + ((lane >> 4) << 3);
    int bcol = (((lane >> 3) & 1) << 3);

    for (int c = 0; c < NCHUNK; c++) {
        if (c < NCHUNK - 1) { CP_WAIT1(); } else { CP_WAIT0(); }
        __syncthreads();
        if (c + 2 < NCHUNK)
            gemm_ld_chunk(gA, gB, sb + ((c + 2) % 3) * STG2, tid, c + 2);

        uint32_t aS = sb + (c % 3) * STG2;
        uint32_t bS = aS + ASTB;

#pragma unroll
        for (int ks = 0; ks < 4; ks++) {
            uint32_t a[4][4];
            uint32_t b[8][2];
#pragma unroll
            for (int mt = 0; mt < 4; mt++) {
                uint32_t ad = aS + (uint32_t)((arow + mt * 16) * SST
                                              + (ks * 16 + acol) * 2);
                LDMX4(a[mt][0], a[mt][1], a[mt][2], a[mt][3], ad);
            }
#pragma unroll
            for (int nh = 0; nh < 4; nh++) {
                uint32_t bd = bS + (uint32_t)((brow + nh * 16) * SST
                                              + (ks * 16 + bcol) * 2);
                LDMX4(b[nh * 2][0], b[nh * 2][1],
                      b[nh * 2 + 1][0], b[nh * 2 + 1][1], bd);
            }
#pragma unroll
            for (int mt = 0; mt < 4; mt++)
#pragma unroll
                for (int nt = 0; nt < 8; nt++)
                    MMA16816(acc[mt][nt], a[mt], b[nt]);
        }
    }
}

// Batched QKV projection GEMM.  z=0: qp fp32 + q2[qh,ql]; z=1: k2[kh,kh];
// z=2: v2 bf16.
__global__ __launch_bounds__(256, 1) void gemm_qkv(
    const __nv_bfloat16* __restrict__ aq, const __nv_bfloat16* __restrict__ ak,
    const __nv_bfloat16* __restrict__ av,
    const __nv_bfloat16* __restrict__ wq, const __nv_bfloat16* __restrict__ wk,
    const __nv_bfloat16* __restrict__ wv,
    const float* __restrict__ bq, const float* __restrict__ bk,
    const float* __restrict__ bv,
    float* __restrict__ qp, __nv_bfloat16* __restrict__ q2,
    __nv_bfloat16* __restrict__ k2, __nv_bfloat16* __restrict__ v2)
{
    extern __shared__ char smem[];
    uint32_t sb = smem_u32(smem);
    int tid  = threadIdx.x;
    int wid  = tid >> 5;
    int lane = tid & 31;
    int bx = blockIdx.x, by = blockIdx.y, z = blockIdx.z;
    int warp_m = wid >> 2, warp_n = wid & 3;

    const __nv_bfloat16* A2 = (z == 0) ? aq : (z == 1) ? ak : av;
    const __nv_bfloat16* B2 = (z == 0) ? wq : (z == 1) ? wk : wv;
    const float* bias       = (z == 0) ? bq : (z == 1) ? bk : bv;

    float acc[4][8][4];
    gemm_core((const char*)(A2 + (size_t)(by * 128) * GK),
              (const char*)(B2 + (size_t)(bx * 256) * GK),
              sb, tid, warp_m, warp_n, lane, acc);

    int g  = lane >> 2;
    int tg = lane & 3;
#pragma unroll
    for (int mt = 0; mt < 4; mt++) {
        int row0 = by * 128 + warp_m * 64 + mt * 16 + g;
#pragma unroll
        for (int nt = 0; nt < 8; nt++) {
            int col = bx * 256 + warp_n * 64 + nt * 8 + tg * 2;
            float2 bv2 = *(const float2*)(bias + col);
            int h = col >> 6, d = col & 63;
#pragma unroll
            for (int half = 0; half < 2; half++) {
                int row = row0 + half * 8;
                float v0 = acc[mt][nt][2 * half]     + bv2.x;
                float v1 = acc[mt][nt][2 * half + 1] + bv2.y;
                int bb = row >> 11, r = row & 2047;
                size_t hb = (size_t)((bb * 16 + h) * 2048 + r);
                __nv_bfloat16 h0, l0, h1, l1;
                split1(v0, h0, l0);
                split1(v1, h1, l1);
                uint32_t hp = pack2(h0, h1);
                uint32_t lp = pack2(l0, l1);
                if (z == 0) {
                    float2 o = {v0, v1};
                    *(float2*)(qp + (size_t)row * Dm + col) = o;
                    size_t base = hb * HD2F;
                    *(uint32_t*)(q2 + base + d)      = hp;   // qh
                    *(uint32_t*)(q2 + base + 64 + d) = lp;   // ql
                } else if (z == 1) {
                    size_t base = hb * HD2F;
                    *(uint32_t*)(k2 + base + d)      = hp;   // kh
                    *(uint32_t*)(k2 + base + 64 + d) = hp;   // kh
                } else {
                    *(uint32_t*)(v2 + hb * DHd + d) = hp;
                }
            }
        }
    }
}

// Output projection GEMM
__global__ __launch_bounds__(256, 1) void gemm_o(
    const __nv_bfloat16* __restrict__ A2, const __nv_bfloat16* __restrict__ B2,
    const float* __restrict__ bias, float* __restrict__ C)
{
    extern __shared__ char smem[];
    uint32_t sb = smem_u32(smem);
    int tid  = threadIdx.x;
    int wid  = tid >> 5;
    int lane = tid & 31;
    int bx = blockIdx.x, by = blockIdx.y;
    int warp_m = wid >> 2, warp_n = wid & 3;

    float acc[4][8][4];
    gemm_core((const char*)(A2 + (size_t)(by * 128) * GK),
              (const char*)(B2 + (size_t)(bx * 256) * GK),
              sb, tid, warp_m, warp_n, lane, acc);

    int g  = lane >> 2;
    int tg = lane & 3;
#pragma unroll
    for (int mt = 0; mt < 4; mt++) {
        int row = by * 128 + warp_m * 64 + mt * 16 + g;
#pragma unroll
        for (int nt = 0; nt < 8; nt++) {
            int col = bx * 256 + warp_n * 64 + nt * 8 + tg * 2;
            float2 bv = *(const float2*)(bias + col);
            float2 o0 = {acc[mt][nt][0] + bv.x, acc[mt][nt][1] + bv.y};
            float2 o1 = {acc[mt][nt][2] + bv.x, acc[mt][nt][3] + bv.y};
            *(float2*)(C + (size_t)row * Dm + col)       = o0;
            *(float2*)(C + (size_t)(row + 8) * Dm + col) = o1;
        }
    }
}

// ============================================================================
// Flash attention, mma.sync bf16; 2-term QK split (d'=128), 3-stage ring
// ============================================================================
#define QROWB 272                  // 128 bf16 = 256 B + 16 pad
#define VROWB 144
#define KTILEB (64 * QROWB)        // 17408
#define VOFF   KTILEB
#define MOFF   (KTILEB + 64 * VROWB)   // 26624
#define STGB   (MOFF + 256)        // 26880
#define FLASH_SMEM (3 * STGB)      // 80640

__device__ __forceinline__ void flash_prefetch(
    uint32_t ds, const char* gK, const char* gV, const char* gM,
    int kt, int tid)
{
    const char* nK = gK + (long)kt * 64 * (HD2F * 2);
    const char* nV = gV + (long)kt * 64 * 128;
#pragma unroll
    for (int it = 0; it < 4; it++) {           // K': 64 rows x 16 chunks16
        int f = tid + it * 256;
        int r = f >> 4, c = f & 15;
        CP_ASYNC16(ds + r * QROWB + c * 16, nK + (long)r * (HD2F * 2) + c * 16);
    }
#pragma unroll
    for (int it = 0; it < 2; it++) {           // V: 64 rows x 8 chunks16
        int f = tid + it * 256;
        int r = f >> 3, c = f & 7;
        CP_ASYNC16(ds + VOFF + r * VROWB + c * 16, nV + (long)r * 128 + c * 16);
    }
    if (tid < 16) CP_ASYNC16(ds + MOFF + tid * 16, gM + kt * 256 + tid * 16);
    CP_COMMIT();
}

__global__ __launch_bounds__(256, 1) void flash_mma(
    const __nv_bfloat16* __restrict__ Q2, const __nv_bfloat16* __restrict__ K2,
    const __nv_bfloat16* __restrict__ V2, const float* __restrict__ MF,
    float* __restrict__ attn)
{
    extern __shared__ char smem[];
    uint32_t sb = smem_u32(smem);
    int tid  = threadIdx.x;
    int wid  = tid >> 5;
    int lane = tid & 31;
    int qx = blockIdx.x, h = blockIdx.y, b = blockIdx.z;

    size_t bh = (size_t)(b * 16 + h) * 2048;
    const char* gQ = (const char*)(Q2 + (bh + qx * 128) * HD2F);
    const char* gK = (const char*)(K2 + bh * HD2F);
    const char* gV = (const char*)(V2 + bh * DHd);
    const char* gM = (const char*)(MF + b * SKL);

    // ---- stage Q' into smem, then ldmatrix into registers ----
#pragma unroll
    for (int it = 0; it < 8; it++) {           // 128 rows x 16 chunks16
        int f = tid + it * 256;
        int r = f >> 4, c = f & 15;
        CP_ASYNC16(sb + r * QROWB + c * 16, gQ + (long)r * (HD2F * 2) + c * 16);
    }
    CP_COMMIT();
    CP_WAIT0();
    __syncthreads();

    uint32_t qf[8][4];
    {
        int arow = wid * 16 + (lane & 15);
        int acol = ((lane >> 4) << 3);
#pragma unroll
        for (int ks = 0; ks < 8; ks++)
            LDMX4(qf[ks][0], qf[ks][1], qf[ks][2], qf[ks][3],
                  sb + arow * QROWB + (ks * 16 + acol) * 2);
    }
    __syncthreads();

    int g  = lane >> 2;
    int tg = lane & 3;

    float O[8][4];
#pragma unroll
    for (int dt = 0; dt < 8; dt++)
#pragma unroll
        for (int r = 0; r < 4; r++) O[dt][r] = 0.f;
    float m0 = -30000.f, m1 = -30000.f, l0 = 0.f, l1 = 0.f;

    const float scale = 0.03125f;

    flash_prefetch(sb,        gK, gV, gM, 0, tid);
    flash_prefetch(sb + STGB, gK, gV, gM, 1, tid);

    int brow = (lane & 7) + ((lane >> 4) << 3);
    int bcol = (((lane >> 3) & 1) << 3);
    int vrow = (lane & 7) + (((lane >> 3) & 1) << 3);
    int vcol = ((lane >> 4) << 3);

    for (int kt = 0; kt < 32; kt++) {
        if (kt < 31) { CP_WAIT1(); } else { CP_WAIT0(); }
        __syncthreads();
        if (kt + 2 < 32)
            flash_prefetch(sb + ((kt + 2) % 3) * STGB, gK, gV, gM, kt + 2, tid);

        uint32_t kS = sb + (kt % 3) * STGB;
        uint32_t vS = kS + VOFF;
        uint32_t mS = kS + MOFF;

        // ---- S = Q' K'^T, flattened (ks 0..7, j 0..3) ----
        float s[8][4];
#pragma unroll
        for (int nt = 0; nt < 8; nt++)
#pragma unroll
            for (int r = 0; r < 4; r++) s[nt][r] = 0.f;

#pragma unroll
        for (int idx = 0; idx < 32; idx++) {
            int ks = idx >> 2, j = idx & 3;
            uint32_t kb[2][2];
            LDMX4(kb[0][0], kb[0][1], kb[1][0], kb[1][1],
                  kS + (uint32_t)((j * 16 + brow) * QROWB
                                  + (ks * 16 + bcol) * 2));
            MMA16816(s[2 * j],     qf[ks], kb[0]);
            MMA16816(s[2 * j + 1], qf[ks], kb[1]);
        }

        // ---- softmax (online) ----
        float mf[8][2];
#pragma unroll
        for (int nt = 0; nt < 8; nt++) {
            mf[nt][0] = *(const float*)((const char*)smem + (mS - sb) + (nt * 8 + 2 * tg) * 4);
            mf[nt][1] = *(const float*)((const char*)smem + (mS - sb) + (nt * 8 + 2 * tg + 1) * 4);
        }
        float rm0 = -30000.f, rm1 = -30000.f;
#pragma unroll
        for (int nt = 0; nt < 8; nt++) {
#pragma unroll
            for (int e = 0; e < 2; e++) {
                float off = (mf[nt][e] - 1.0f) * 30000.f;
                s[nt][e]     = s[nt][e]     * scale + off;
                s[nt][2 + e] = s[nt][2 + e] * scale + off;
                rm0 = fmaxf(rm0, s[nt][e]);
                rm1 = fmaxf(rm1, s[nt][2 + e]);
            }
        }
        rm0 = fmaxf(rm0, __shfl_xor_sync(0xffffffffu, rm0, 1));
        rm0 = fmaxf(rm0, __shfl_xor_sync(0xffffffffu, rm0, 2));
        rm1 = fmaxf(rm1, __shfl_xor_sync(0xffffffffu, rm1, 1));
        rm1 = fmaxf(rm1, __shfl_xor_sync(0xffffffffu, rm1, 2));

        float mn0 = fmaxf(m0, rm0), mn1 = fmaxf(m1, rm1);
        float al0 = __expf(m0 - mn0), al1 = __expf(m1 - mn1);
        m0 = mn0; m1 = mn1;

        float rs0 = 0.f, rs1 = 0.f;
#pragma unroll
        for (int nt = 0; nt < 8; nt++) {
#pragma unroll
            for (int e = 0; e < 2; e++) {
                float p0 = __expf(s[nt][e]     - mn0) * mf[nt][e];
                float p1 = __expf(s[nt][2 + e] - mn1) * mf[nt][e];
                s[nt][e] = p0;  s[nt][2 + e] = p1;
                rs0 += p0;  rs1 += p1;
            }
        }
        rs0 += __shfl_xor_sync(0xffffffffu, rs0, 1);
        rs0 += __shfl_xor_sync(0xffffffffu, rs0, 2);
        rs1 += __shfl_xor_sync(0xffffffffu, rs1, 1);
        rs1 += __shfl_xor_sync(0xffffffffu, rs1, 2);
        l0 = l0 * al0 + rs0;
        l1 = l1 * al1 + rs1;

#pragma unroll
        for (int dt = 0; dt < 8; dt++) {
            O[dt][0] *= al0; O[dt][1] *= al0;
            O[dt][2] *= al1; O[dt][3] *= al1;
        }

        // ---- O += P V ----
        uint32_t pa[4][4];
#pragma unroll
        for (int ks = 0; ks < 4; ks++) {
            pa[ks][0] = packbf(s[2 * ks][0],     s[2 * ks][1]);
            pa[ks][1] = packbf(s[2 * ks][2],     s[2 * ks][3]);
            pa[ks][2] = packbf(s[2 * ks + 1][0], s[2 * ks + 1][1]);
            pa[ks][3] = packbf(s[2 * ks + 1][2], s[2 * ks + 1][3]);
        }
#pragma unroll
        for (int idx = 0; idx < 16; idx++) {
            int ks = idx >> 2, j = idx & 3;
            uint32_t vb[2][2];
            LDMX4T(vb[0][0], vb[0][1], vb[1][0], vb[1][1],
                   vS + (uint32_t)((ks * 16 + vrow) * VROWB
                                   + (j * 16 + vcol) * 2));
            MMA16816(O[2 * j],     pa[ks], vb[0]);
            MMA16816(O[2 * j + 1], pa[ks], vb[1]);
        }
    }

    float inv0 = l0 > 0.f ? 1.f / l0 : 0.f;
    float inv1 = l1 > 0.f ? 1.f / l1 : 0.f;
    int row0 = qx * 128 + wid * 16 + g;
    float* oBase = attn + (size_t)(b * SQL) * Dm + h * DHd;
#pragma unroll
    for (int dt = 0; dt < 8; dt++) {
        int col = dt * 8 + 2 * tg;
        float2 o0 = {O[dt][0] * inv0, O[dt][1] * inv0};
        float2 o1 = {O[dt][2] * inv1, O[dt][3] * inv1};
        *(float2*)(oBase + (size_t)row0 * Dm + col)       = o0;
        *(float2*)(oBase + (size_t)(row0 + 8) * Dm + col) = o1;
    }
}

// ============================================================================
// out = LayerNorm(X + (relu? relu(Y) : Y)) * g + beta; optional split output
// ============================================================================
__global__ __launch_bounds__(256) void add_ln(
    const float* __restrict__ X, const float* __restrict__ Y,
    const float* __restrict__ g, const float* __restrict__ be,
    float* __restrict__ out, __nv_bfloat16* __restrict__ a2, int dorelu)
{
    int row = blockIdx.x;
    int tid = threadIdx.x;
    size_t base = (size_t)row * Dm + tid * 4;

    float4 x4 = *(const float4*)(X + base);
    float4 y4 = *(const float4*)(Y + base);
    if (dorelu) {
        y4.x = fmaxf(y4.x, 0.f); y4.y = fmaxf(y4.y, 0.f);
        y4.z = fmaxf(y4.z, 0.f); y4.w = fmaxf(y4.w, 0.f);
    }
    float v[4] = {x4.x + y4.x, x4.y + y4.y, x4.z + y4.z, x4.w + y4.w};

    float s  = v[0] + v[1] + v[2] + v[3];
    float sq = v[0]*v[0] + v[1]*v[1] + v[2]*v[2] + v[3]*v[3];
#pragma unroll
    for (int off = 16; off > 0; off >>= 1) {
        s  += __shfl_xor_sync(0xffffffffu, s,  off);
        sq += __shfl_xor_sync(0xffffffffu, sq, off);
    }
    __shared__ float sh[16];
    int w = tid >> 5;
    if ((tid & 31) == 0) { sh[w] = s; sh[8 + w] = sq; }
    __syncthreads();
    s = 0.f; sq = 0.f;
#pragma unroll
    for (int i = 0; i < 8; i++) { s += sh[i]; sq += sh[8 + i]; }

    float mean = s * (1.f / 1024.f);
    float var  = fmaf(-mean, mean, sq * (1.f / 1024.f));
    float rstd = rsqrtf(var + 1e-6f);

    float4 g4 = *(const float4*)(g  + tid * 4);
    float4 b4 = *(const float4*)(be + tid * 4);
    float o[4];
    o[0] = (v[0] - mean) * rstd * g4.x + b4.x;
    o[1] = (v[1] - mean) * rstd * g4.y + b4.y;
    o[2] = (v[2] - mean) * rstd * g4.z + b4.z;
    o[3] = (v[3] - mean) * rstd * g4.w + b4.w;
    *(float4*)(out + base) = *(float4*)o;

    if (a2) {
        size_t ab = (size_t)row * GK + tid * 4;
        __nv_bfloat16 h0, l0, h1, l1, h2, l2, h3, l3;
        split1(o[0], h0, l0); split1(o[1], h1, l1);
        split1(o[2], h2, l2); split1(o[3], h3, l3);
        uint2 hp = make_uint2(pack2(h0, h1), pack2(h2, h3));
        uint2 lp = make_uint2(pack2(l0, l1), pack2(l2, l3));
        *(uint2*)(a2 + ab)        = hp;
        *(uint2*)(a2 + ab + 1024) = lp;
        *(uint2*)(a2 + ab + 2048) = hp;
    }
}

// ============================================================================
extern "C" void kernel_launch(void* const* d_in, const int* in_sizes, int n_in,
                              void* d_out, int out_size)
{
    const float* q    = (const float*)d_in[0];
    const float* k    = (const float*)d_in[1];
    const float* v    = (const float*)d_in[2];
    const int*   mask = (const int*)d_in[3];
    const float* Wq   = (const float*)d_in[4];
    const float* bq   = (const float*)d_in[5];
    const float* Wk   = (const float*)d_in[6];
    const float* bk   = (const float*)d_in[7];
    const float* Wv   = (const float*)d_in[8];
    const float* bv   = (const float*)d_in[9];
    const float* Wo   = (const float*)d_in[10];
    const float* bo   = (const float*)d_in[11];
    const float* g1   = (const float*)d_in[12];
    const float* b1   = (const float*)d_in[13];
    const float* g2   = (const float*)d_in[14];
    const float* b2   = (const float*)d_in[15];

    float *qp, *at, *x, *y, *mf;
    __nv_bfloat16 *aq, *ak, *av, *w2q, *w2k, *w2v, *w2o, *q2, *k2, *v2;
    cudaGetSymbolAddress((void**)&qp, g_qp);
    cudaGetSymbolAddress((void**)&at, g_att);
    cudaGetSymbolAddress((void**)&x,  g_x);
    cudaGetSymbolAddress((void**)&y,  g_y);
    cudaGetSymbolAddress((void**)&aq,  g_a2q);
    cudaGetSymbolAddress((void**)&ak,  g_a2k);
    cudaGetSymbolAddress((void**)&av,  g_a2v);
    cudaGetSymbolAddress((void**)&w2q, g_w2q);
    cudaGetSymbolAddress((void**)&w2k, g_w2k);
    cudaGetSymbolAddress((void**)&w2v, g_w2v);
    cudaGetSymbolAddress((void**)&w2o, g_w2o);
    cudaGetSymbolAddress((void**)&q2,  g_q2x);
    cudaGetSymbolAddress((void**)&k2,  g_k2x);
    cudaGetSymbolAddress((void**)&v2,  g_v2x);
    cudaGetSymbolAddress((void**)&mf,  g_mf);

    cudaFuncSetAttribute(gemm_qkv, cudaFuncAttributeMaxDynamicSharedMemorySize,
                         GEMM_SMEM);
    cudaFuncSetAttribute(gemm_o, cudaFuncAttributeMaxDynamicSharedMemorySize,
                         GEMM_SMEM);
    cudaFuncSetAttribute(flash_mma, cudaFuncAttributeMaxDynamicSharedMemorySize,
                         FLASH_SMEM);

    conv_w4<<<dim3(Dm / 32, Dm / 32, 4), dim3(32, 8)>>>(
        Wq, Wk, Wv, Wo, w2q, w2k, w2v, w2o);

    int cab4 = (int)(((size_t)NR * Dm) / 1024);
    conv_a3<<<dim3(cab4, 1, 3), 256>>>(q, k, v, aq, ak, av);
    conv_mask<<<(Bz * SKL + 255) / 256, 256>>>(mask, mf);

    gemm_qkv<<<dim3(Dm / 256, NR / 128, 3), 256, GEMM_SMEM>>>(
        aq, ak, av, w2q, w2k, w2v, bq, bk, bv, qp, q2, k2, v2);

    flash_mma<<<dim3(SQL / 128, Hh, Bz), 256, FLASH_SMEM>>>(q2, k2, v2, mf, at);

    add_ln<<<NR, 256>>>(qp, at, g1, b1, x, aq, 0);

    gemm_o<<<dim3(Dm / 256, NR / 128), 256, GEMM_SMEM>>>(aq, w2o, bo, y);

    add_ln<<<NR, 256>>>(x, y, g2, b2, (float*)d_out, (__nv_bfloat16*)0, 1);
}

// round 15
// speedup vs baseline: 1.1247x; 1.1206x over previous
#include <cuda_runtime.h>
#include <cuda_bf16.h>
#include <cstdint>
#include <math.h>

// Problem constants
#define Bz   4
#define SQL  2048
#define SKL  2048
#define Dm   1024
#define Hh   16
#define DHd  64
#define NR   (Bz*SQL)          // 8192 rows
#define GK   3072              // weight split K' = 3*1024
#define GKA  2048              // activation split storage (hi, lo)
#define NCHUNK 48
#define HD2F 128               // flash Q split head dim 2*64

// -------- scratch (device globals; no allocation allowed) --------
__device__ float g_qp [NR*Dm];
__device__ float g_att[NR*Dm];
__device__ float g_x  [NR*Dm];
__device__ float g_y  [NR*Dm];
__device__ __nv_bfloat16 g_a2q[(size_t)NR*GKA];
__device__ __nv_bfloat16 g_a2k[(size_t)NR*GKA];
__device__ __nv_bfloat16 g_a2v[(size_t)NR*GKA];
__device__ __nv_bfloat16 g_w2q[(size_t)Dm*GK];
__device__ __nv_bfloat16 g_w2k[(size_t)Dm*GK];
__device__ __nv_bfloat16 g_w2v[(size_t)Dm*GK];
__device__ __nv_bfloat16 g_w2o[(size_t)Dm*GK];
__device__ __nv_bfloat16 g_q2x[(size_t)Bz*Hh*SQL*HD2F];
__device__ __nv_bfloat16 g_k2x[(size_t)Bz*Hh*SKL*DHd];
__device__ __nv_bfloat16 g_v2x[(size_t)Bz*Hh*SKL*DHd];
__device__ float g_mf [Bz*SKL];

// ============================================================================
// helpers
// ============================================================================
__device__ __forceinline__ uint32_t smem_u32(const void* p) {
    uint32_t a;
    asm("{ .reg .u64 t; cvta.to.shared.u64 t, %1; cvt.u32.u64 %0, t; }"
        : "=r"(a) : "l"(p));
    return a;
}
#define CP_ASYNC16(saddr, gptr) \
    asm volatile("cp.async.cg.shared.global [%0], [%1], 16;" \
                 :: "r"(saddr), "l"(gptr))
#define CP_COMMIT() asm volatile("cp.async.commit_group;" ::: "memory")
#define CP_WAIT1()  asm volatile("cp.async.wait_group 1;" ::: "memory")
#define CP_WAIT0()  asm volatile("cp.async.wait_group 0;" ::: "memory")

#define LDMX4(r0,r1,r2,r3,addr) \
    asm volatile("ldmatrix.sync.aligned.m8n8.x4.shared.b16 {%0,%1,%2,%3}, [%4];" \
                 : "=r"(r0), "=r"(r1), "=r"(r2), "=r"(r3) : "r"(addr))
#define LDMX4T(r0,r1,r2,r3,addr) \
    asm volatile("ldmatrix.sync.aligned.m8n8.x4.trans.shared.b16 {%0,%1,%2,%3}, [%4];" \
                 : "=r"(r0), "=r"(r1), "=r"(r2), "=r"(r3) : "r"(addr))

#define MMA16816(d, a, b) \
    asm volatile("mma.sync.aligned.m16n8k16.row.col.f32.bf16.bf16.f32 " \
                 "{%0,%1,%2,%3}, {%4,%5,%6,%7}, {%8,%9}, {%0,%1,%2,%3};" \
                 : "+f"((d)[0]), "+f"((d)[1]), "+f"((d)[2]), "+f"((d)[3]) \
                 : "r"((a)[0]), "r"((a)[1]), "r"((a)[2]), "r"((a)[3]), \
                   "r"((b)[0]), "r"((b)[1]))

__device__ __forceinline__ uint32_t packbf(float a, float b) {
    __nv_bfloat162 t = __floats2bfloat162_rn(a, b);
    return *(uint32_t*)&t;
}
__device__ __forceinline__ void split1(float v, __nv_bfloat16& hi, __nv_bfloat16& lo) {
    hi = __float2bfloat16(v);
    lo = __float2bfloat16(v - __bfloat162float(hi));
}
__device__ __forceinline__ uint32_t pack2(__nv_bfloat16 a, __nv_bfloat16 b) {
    return (uint32_t)(*(uint16_t*)&a) | ((uint32_t)(*(uint16_t*)&b) << 16);
}

// ============================================================================
// conversion kernels
// ============================================================================
// a2 layout: [hi(1024), lo(1024)] per row (hi re-read for third K section)
__global__ __launch_bounds__(256) void conv_a3(
    const float* __restrict__ q, const float* __restrict__ k,
    const float* __restrict__ v,
    __nv_bfloat16* __restrict__ aq, __nv_bfloat16* __restrict__ ak,
    __nv_bfloat16* __restrict__ av)
{
    int z = blockIdx.z;
    const float* A = (z == 0) ? q : (z == 1) ? k : v;
    __nv_bfloat16* A2 = (z == 0) ? aq : (z == 1) ? ak : av;
    size_t i4 = (size_t)blockIdx.x * 256 + threadIdx.x;
    size_t e  = i4 * 4;
    int row = (int)(e >> 10);
    int kk  = (int)(e & 1023);
    float4 vv = *(const float4*)(A + e);
    __nv_bfloat16 h0, l0, h1, l1, h2, l2, h3, l3;
    split1(vv.x, h0, l0); split1(vv.y, h1, l1);
    split1(vv.z, h2, l2); split1(vv.w, h3, l3);
    uint2 hp = make_uint2(pack2(h0, h1), pack2(h2, h3));
    uint2 lp = make_uint2(pack2(l0, l1), pack2(l2, l3));
    size_t base = (size_t)row * GKA + kk;
    *(uint2*)(A2 + base)        = hp;
    *(uint2*)(A2 + base + 1024) = lp;
}

__global__ __launch_bounds__(256) void conv_w4(
    const float* __restrict__ Wq, const float* __restrict__ Wk,
    const float* __restrict__ Wv, const float* __restrict__ Wo,
    __nv_bfloat16* __restrict__ Tq, __nv_bfloat16* __restrict__ Tk,
    __nv_bfloat16* __restrict__ Tv, __nv_bfloat16* __restrict__ To)
{
    int z = blockIdx.z;
    const float* W = (z == 0) ? Wq : (z == 1) ? Wk : (z == 2) ? Wv : Wo;
    __nv_bfloat16* Wt = (z == 0) ? Tq : (z == 1) ? Tk : (z == 2) ? Tv : To;
    __shared__ float t[32][33];
    int tx = threadIdx.x, ty = threadIdx.y;
    int n0 = blockIdx.x * 32, k0 = blockIdx.y * 32;
#pragma unroll
    for (int i = 0; i < 4; i++)
        t[ty * 4 + i][tx] = W[(size_t)(k0 + ty * 4 + i) * Dm + n0 + tx];
    __syncthreads();
#pragma unroll
    for (int i = 0; i < 4; i++) {
        int n = ty * 4 + i;
        __nv_bfloat16 hi, lo;
        split1(t[tx][n], hi, lo);
        size_t base = (size_t)(n0 + n) * GK;
        Wt[base + k0 + tx]        = hi;
        Wt[base + 1024 + k0 + tx] = hi;
        Wt[base + 2048 + k0 + tx] = lo;
    }
}

__global__ __launch_bounds__(256) void conv_mask(
    const int* __restrict__ m, float* __restrict__ mf)
{
    int i = blockIdx.x * 256 + threadIdx.x;
    if (i < Bz * SKL) mf[i] = m[i] ? 1.0f : 0.0f;
}

// ============================================================================
// GEMM core: 128x128 tile, 64x32 warp tiles, 3-stage cp.async, 2 CTAs/SM
// A chunks remapped: c>=32 re-reads hi section (c-32)
// ============================================================================
#define SST   144
#define MATB  (128 * SST)
#define STAGEB (2 * MATB)          // 36864
#define GEMM_SMEM (3 * STAGEB)     // 110592

__device__ __forceinline__ void gemm_ld_chunk(
    const char* gA, const char* gB, uint32_t as, int tid, int c)
{
    uint32_t bs = as + MATB;
    int acb = ((c < 32) ? c : c - 32) * 128;
    int bcb = c * 128;
#pragma unroll
    for (int it = 0; it < 4; it++) {
        int f = tid + it * 256;
        int r = f >> 3, col = (f & 7) * 16;
        uint32_t so = (uint32_t)(r * SST + col);
        CP_ASYNC16(as + so, gA + (long)r * (GKA * 2) + acb + col);
        CP_ASYNC16(bs + so, gB + (long)r * (GK * 2) + bcb + col);
    }
    CP_COMMIT();
}

__device__ __forceinline__ void gemm_core(
    const char* gA, const char* gB, uint32_t sb, int tid,
    int warp_m, int warp_n, int lane, float acc[4][4][4])
{
#pragma unroll
    for (int mt = 0; mt < 4; mt++)
#pragma unroll
        for (int nt = 0; nt < 4; nt++)
#pragma unroll
            for (int r = 0; r < 4; r++) acc[mt][nt][r] = 0.f;

    gemm_ld_chunk(gA, gB, sb, tid, 0);
    gemm_ld_chunk(gA, gB, sb + STAGEB, tid, 1);

    int arow = warp_m * 64 + (lane & 15);
    int acol = ((lane >> 4) << 3);
    int brow = warp_n * 32 + (lane & 7) + ((lane >> 4) << 3);
    int bcol = (((lane >> 3) & 1) << 3);

    for (int c = 0; c < NCHUNK; c++) {
        if (c < NCHUNK - 1) { CP_WAIT1(); } else { CP_WAIT0(); }
        __syncthreads();
        if (c + 2 < NCHUNK)
            gemm_ld_chunk(gA, gB, sb + ((c + 2) % 3) * STAGEB, tid, c + 2);

        uint32_t aS = sb + (c % 3) * STAGEB;
        uint32_t bS = aS + MATB;

#pragma unroll
        for (int ks = 0; ks < 4; ks++) {
            uint32_t a[4][4];
            uint32_t b[4][2];
#pragma unroll
            for (int mt = 0; mt < 4; mt++) {
                uint32_t ad = aS + (uint32_t)((arow + mt * 16) * SST
                                              + (ks * 16 + acol) * 2);
                LDMX4(a[mt][0], a[mt][1], a[mt][2], a[mt][3], ad);
            }
#pragma unroll
            for (int nh = 0; nh < 2; nh++) {
                uint32_t bd = bS + (uint32_t)((brow + nh * 16) * SST
                                              + (ks * 16 + bcol) * 2);
                LDMX4(b[nh * 2][0], b[nh * 2][1],
                      b[nh * 2 + 1][0], b[nh * 2 + 1][1], bd);
            }
#pragma unroll
            for (int mt = 0; mt < 4; mt++)
#pragma unroll
                for (int nt = 0; nt < 4; nt++)
                    MMA16816(acc[mt][nt], a[mt], b[nt]);
        }
    }
}

// Batched QKV projection GEMM. z=0: qp fp32 + q2[qh,ql]; z=1: k2[kh]; z=2: v2.
__global__ __launch_bounds__(256) void gemm_qkv(
    const __nv_bfloat16* __restrict__ aq, const __nv_bfloat16* __restrict__ ak,
    const __nv_bfloat16* __restrict__ av,
    const __nv_bfloat16* __restrict__ wq, const __nv_bfloat16* __restrict__ wk,
    const __nv_bfloat16* __restrict__ wv,
    const float* __restrict__ bq, const float* __restrict__ bk,
    const float* __restrict__ bv,
    float* __restrict__ qp, __nv_bfloat16* __restrict__ q2,
    __nv_bfloat16* __restrict__ k2, __nv_bfloat16* __restrict__ v2)
{
    extern __shared__ char smem[];
    uint32_t sb = smem_u32(smem);
    int tid  = threadIdx.x;
    int wid  = tid >> 5;
    int lane = tid & 31;
    int bx = blockIdx.x, by = blockIdx.y, z = blockIdx.z;
    int warp_m = wid >> 2, warp_n = wid & 3;

    const __nv_bfloat16* A2 = (z == 0) ? aq : (z == 1) ? ak : av;
    const __nv_bfloat16* B2 = (z == 0) ? wq : (z == 1) ? wk : wv;
    const float* bias       = (z == 0) ? bq : (z == 1) ? bk : bv;

    float acc[4][4][4];
    gemm_core((const char*)(A2 + (size_t)(by * 128) * GKA),
              (const char*)(B2 + (size_t)(bx * 128) * GK),
              sb, tid, warp_m, warp_n, lane, acc);

    int g  = lane >> 2;
    int tg = lane & 3;
#pragma unroll
    for (int mt = 0; mt < 4; mt++) {
        int row0 = by * 128 + warp_m * 64 + mt * 16 + g;
#pragma unroll
        for (int nt = 0; nt < 4; nt++) {
            int col = bx * 128 + warp_n * 32 + nt * 8 + tg * 2;
            float2 bv2 = *(const float2*)(bias + col);
            int h = col >> 6, d = col & 63;
#pragma unroll
            for (int half = 0; half < 2; half++) {
                int row = row0 + half * 8;
                float v0 = acc[mt][nt][2 * half]     + bv2.x;
                float v1 = acc[mt][nt][2 * half + 1] + bv2.y;
                int bb = row >> 11, r = row & 2047;
                size_t hb = (size_t)((bb * 16 + h) * 2048 + r);
                __nv_bfloat16 h0, l0, h1, l1;
                split1(v0, h0, l0);
                split1(v1, h1, l1);
                uint32_t hp = pack2(h0, h1);
                uint32_t lp = pack2(l0, l1);
                if (z == 0) {
                    float2 o = {v0, v1};
                    *(float2*)(qp + (size_t)row * Dm + col) = o;
                    size_t base = hb * HD2F;
                    *(uint32_t*)(q2 + base + d)      = hp;   // qh
                    *(uint32_t*)(q2 + base + 64 + d) = lp;   // ql
                } else if (z == 1) {
                    *(uint32_t*)(k2 + hb * DHd + d) = hp;    // kh (single copy)
                } else {
                    *(uint32_t*)(v2 + hb * DHd + d) = hp;
                }
            }
        }
    }
}

// Output projection GEMM
__global__ __launch_bounds__(256) void gemm_o(
    const __nv_bfloat16* __restrict__ A2, const __nv_bfloat16* __restrict__ B2,
    const float* __restrict__ bias, float* __restrict__ C)
{
    extern __shared__ char smem[];
    uint32_t sb = smem_u32(smem);
    int tid  = threadIdx.x;
    int wid  = tid >> 5;
    int lane = tid & 31;
    int bx = blockIdx.x, by = blockIdx.y;
    int warp_m = wid >> 2, warp_n = wid & 3;

    float acc[4][4][4];
    gemm_core((const char*)(A2 + (size_t)(by * 128) * GKA),
              (const char*)(B2 + (size_t)(bx * 128) * GK),
              sb, tid, warp_m, warp_n, lane, acc);

    int g  = lane >> 2;
    int tg = lane & 3;
#pragma unroll
    for (int mt = 0; mt < 4; mt++) {
        int row = by * 128 + warp_m * 64 + mt * 16 + g;
#pragma unroll
        for (int nt = 0; nt < 4; nt++) {
            int col = bx * 128 + warp_n * 32 + nt * 8 + tg * 2;
            float2 bv = *(const float2*)(bias + col);
            float2 o0 = {acc[mt][nt][0] + bv.x, acc[mt][nt][1] + bv.y};
            float2 o1 = {acc[mt][nt][2] + bv.x, acc[mt][nt][3] + bv.y};
            *(float2*)(C + (size_t)row * Dm + col)       = o0;
            *(float2*)(C + (size_t)(row + 8) * Dm + col) = o1;
        }
    }
}

// ============================================================================
// Flash attention: Q split [qh,ql] vs single-copy K (same K frags reused)
// ============================================================================
#define QROWB 272                  // Q staging row: 128 bf16 + pad
#define KROWB 144                  // K tile row: 64 bf16 + pad
#define VROWB 144
#define KTILEB (64 * KROWB)        // 9216
#define VOFF   KTILEB
#define MOFF   (KTILEB + 64 * VROWB)   // 18432
#define STGB   (MOFF + 256)        // 18688
#define FLASH_SMEM (3 * STGB)      // 56064  (Q staging 34816 fits)

__device__ __forceinline__ void flash_prefetch(
    uint32_t ds, const char* gK, const char* gV, const char* gM,
    int kt, int tid)
{
    const char* nK = gK + (long)kt * 64 * 128;
    const char* nV = gV + (long)kt * 64 * 128;
#pragma unroll
    for (int it = 0; it < 2; it++) {           // K: 64 rows x 8 chunks16
        int f = tid + it * 256;
        int r = f >> 3, c = f & 7;
        CP_ASYNC16(ds + r * KROWB + c * 16, nK + (long)r * 128 + c * 16);
    }
#pragma unroll
    for (int it = 0; it < 2; it++) {           // V: 64 rows x 8 chunks16
        int f = tid + it * 256;
        int r = f >> 3, c = f & 7;
        CP_ASYNC16(ds + VOFF + r * VROWB + c * 16, nV + (long)r * 128 + c * 16);
    }
    if (tid < 16) CP_ASYNC16(ds + MOFF + tid * 16, gM + kt * 256 + tid * 16);
    CP_COMMIT();
}

__global__ __launch_bounds__(256, 1) void flash_mma(
    const __nv_bfloat16* __restrict__ Q2, const __nv_bfloat16* __restrict__ K2,
    const __nv_bfloat16* __restrict__ V2, const float* __restrict__ MF,
    float* __restrict__ attn)
{
    extern __shared__ char smem[];
    uint32_t sb = smem_u32(smem);
    int tid  = threadIdx.x;
    int wid  = tid >> 5;
    int lane = tid & 31;
    int qx = blockIdx.x, h = blockIdx.y, b = blockIdx.z;

    size_t bh = (size_t)(b * 16 + h) * 2048;
    const char* gQ = (const char*)(Q2 + (bh + qx * 128) * HD2F);
    const char* gK = (const char*)(K2 + bh * DHd);
    const char* gV = (const char*)(V2 + bh * DHd);
    const char* gM = (const char*)(MF + b * SKL);

    // ---- stage Q' into smem, then ldmatrix into registers ----
#pragma unroll
    for (int it = 0; it < 8; it++) {
        int f = tid + it * 256;
        int r = f >> 4, c = f & 15;
        CP_ASYNC16(sb + r * QROWB + c * 16, gQ + (long)r * (HD2F * 2) + c * 16);
    }
    CP_COMMIT();
    CP_WAIT0();
    __syncthreads();

    uint32_t qf[8][4];           // ks 0..3 = qh, ks 4..7 = ql
    {
        int arow = wid * 16 + (lane & 15);
        int acol = ((lane >> 4) << 3);
#pragma unroll
        for (int ks = 0; ks < 8; ks++)
            LDMX4(qf[ks][0], qf[ks][1], qf[ks][2], qf[ks][3],
                  sb + arow * QROWB + (ks * 16 + acol) * 2);
    }
    __syncthreads();

    int g  = lane >> 2;
    int tg = lane & 3;

    float O[8][4];
#pragma unroll
    for (int dt = 0; dt < 8; dt++)
#pragma unroll
        for (int r = 0; r < 4; r++) O[dt][r] = 0.f;
    float m0 = -30000.f, m1 = -30000.f, l0 = 0.f, l1 = 0.f;

    const float scale = 0.03125f;

    flash_prefetch(sb,        gK, gV, gM, 0, tid);
    flash_prefetch(sb + STGB, gK, gV, gM, 1, tid);

    int brow = (lane & 7) + ((lane >> 4) << 3);
    int bcol = (((lane >> 3) & 1) << 3);
    int vrow = (lane & 7) + (((lane >> 3) & 1) << 3);
    int vcol = ((lane >> 4) << 3);

    for (int kt = 0; kt < 32; kt++) {
        if (kt < 31) { CP_WAIT1(); } else { CP_WAIT0(); }
        __syncthreads();
        if (kt + 2 < 32)
            flash_prefetch(sb + ((kt + 2) % 3) * STGB, gK, gV, gM, kt + 2, tid);

        uint32_t kS = sb + (kt % 3) * STGB;
        uint32_t vS = kS + VOFF;
        uint32_t mS = kS + MOFF;

        // ---- S = qh K^T + ql K^T (same K fragments) ----
        float s[8][4];
#pragma unroll
        for (int nt = 0; nt < 8; nt++)
#pragma unroll
            for (int r = 0; r < 4; r++) s[nt][r] = 0.f;

#pragma unroll
        for (int idx = 0; idx < 16; idx++) {
            int ks = idx >> 2, j = idx & 3;
            uint32_t kb[2][2];
            LDMX4(kb[0][0], kb[0][1], kb[1][0], kb[1][1],
                  kS + (uint32_t)((j * 16 + brow) * KROWB
                                  + (ks * 16 + bcol) * 2));
            MMA16816(s[2 * j],     qf[ks],     kb[0]);
            MMA16816(s[2 * j + 1], qf[ks],     kb[1]);
            MMA16816(s[2 * j],     qf[ks + 4], kb[0]);
            MMA16816(s[2 * j + 1], qf[ks + 4], kb[1]);
        }

        // ---- softmax (online) ----
        float mf[8][2];
#pragma unroll
        for (int nt = 0; nt < 8; nt++) {
            mf[nt][0] = *(const float*)((const char*)smem + (mS - sb) + (nt * 8 + 2 * tg) * 4);
            mf[nt][1] = *(const float*)((const char*)smem + (mS - sb) + (nt * 8 + 2 * tg + 1) * 4);
        }
        float rm0 = -30000.f, rm1 = -30000.f;
#pragma unroll
        for (int nt = 0; nt < 8; nt++) {
#pragma unroll
            for (int e = 0; e < 2; e++) {
                float off = (mf[nt][e] - 1.0f) * 30000.f;
                s[nt][e]     = s[nt][e]     * scale + off;
                s[nt][2 + e] = s[nt][2 + e] * scale + off;
                rm0 = fmaxf(rm0, s[nt][e]);
                rm1 = fmaxf(rm1, s[nt][2 + e]);
            }
        }
        rm0 = fmaxf(rm0, __shfl_xor_sync(0xffffffffu, rm0, 1));
        rm0 = fmaxf(rm0, __shfl_xor_sync(0xffffffffu, rm0, 2));
        rm1 = fmaxf(rm1, __shfl_xor_sync(0xffffffffu, rm1, 1));
        rm1 = fmaxf(rm1, __shfl_xor_sync(0xffffffffu, rm1, 2));

        float mn0 = fmaxf(m0, rm0), mn1 = fmaxf(m1, rm1);
        float al0 = __expf(m0 - mn0), al1 = __expf(m1 - mn1);
        m0 = mn0; m1 = mn1;

        float rs0 = 0.f, rs1 = 0.f;
#pragma unroll
        for (int nt = 0; nt < 8; nt++) {
#pragma unroll
            for (int e = 0; e < 2; e++) {
                float p0 = __expf(s[nt][e]     - mn0) * mf[nt][e];
                float p1 = __expf(s[nt][2 + e] - mn1) * mf[nt][e];
                s[nt][e] = p0;  s[nt][2 + e] = p1;
                rs0 += p0;  rs1 += p1;
            }
        }
        rs0 += __shfl_xor_sync(0xffffffffu, rs0, 1);
        rs0 += __shfl_xor_sync(0xffffffffu, rs0, 2);
        rs1 += __shfl_xor_sync(0xffffffffu, rs1, 1);
        rs1 += __shfl_xor_sync(0xffffffffu, rs1, 2);
        l0 = l0 * al0 + rs0;
        l1 = l1 * al1 + rs1;

#pragma unroll
        for (int dt = 0; dt < 8; dt++) {
            O[dt][0] *= al0; O[dt][1] *= al0;
            O[dt][2] *= al1; O[dt][3] *= al1;
        }

        // ---- O += P V ----
        uint32_t pa[4][4];
#pragma unroll
        for (int ks = 0; ks < 4; ks++) {
            pa[ks][0] = packbf(s[2 * ks][0],     s[2 * ks][1]);
            pa[ks][1] = packbf(s[2 * ks][2],     s[2 * ks][3]);
            pa[ks][2] = packbf(s[2 * ks + 1][0], s[2 * ks + 1][1]);
            pa[ks][3] = packbf(s[2 * ks + 1][2], s[2 * ks + 1][3]);
        }
#pragma unroll
        for (int idx = 0; idx < 16; idx++) {
            int ks = idx >> 2, j = idx & 3;
            uint32_t vb[2][2];
            LDMX4T(vb[0][0], vb[0][1], vb[1][0], vb[1][1],
                   vS + (uint32_t)((ks * 16 + vrow) * VROWB
                                   + (j * 16 + vcol) * 2));
            MMA16816(O[2 * j],     pa[ks], vb[0]);
            MMA16816(O[2 * j + 1], pa[ks], vb[1]);
        }
    }

    float inv0 = l0 > 0.f ? 1.f / l0 : 0.f;
    float inv1 = l1 > 0.f ? 1.f / l1 : 0.f;
    int row0 = qx * 128 + wid * 16 + g;
    float* oBase = attn + (size_t)(b * SQL) * Dm + h * DHd;
#pragma unroll
    for (int dt = 0; dt < 8; dt++) {
        int col = dt * 8 + 2 * tg;
        float2 o0 = {O[dt][0] * inv0, O[dt][1] * inv0};
        float2 o1 = {O[dt][2] * inv1, O[dt][3] * inv1};
        *(float2*)(oBase + (size_t)row0 * Dm + col)       = o0;
        *(float2*)(oBase + (size_t)(row0 + 8) * Dm + col) = o1;
    }
}

// ============================================================================
// out = LayerNorm(X + (relu? relu(Y) : Y)) * g + beta; optional split output
// ============================================================================
__global__ __launch_bounds__(256) void add_ln(
    const float* __restrict__ X, const float* __restrict__ Y,
    const float* __restrict__ g, const float* __restrict__ be,
    float* __restrict__ out, __nv_bfloat16* __restrict__ a2, int dorelu)
{
    int row = blockIdx.x;
    int tid = threadIdx.x;
    size_t base = (size_t)row * Dm + tid * 4;

    float4 x4 = *(const float4*)(X + base);
    float4 y4 = *(const float4*)(Y + base);
    if (dorelu) {
        y4.x = fmaxf(y4.x, 0.f); y4.y = fmaxf(y4.y, 0.f);
        y4.z = fmaxf(y4.z, 0.f); y4.w = fmaxf(y4.w, 0.f);
    }
    float v[4] = {x4.x + y4.x, x4.y + y4.y, x4.z + y4.z, x4.w + y4.w};

    float s  = v[0] + v[1] + v[2] + v[3];
    float sq = v[0]*v[0] + v[1]*v[1] + v[2]*v[2] + v[3]*v[3];
#pragma unroll
    for (int off = 16; off > 0; off >>= 1) {
        s  += __shfl_xor_sync(0xffffffffu, s,  off);
        sq += __shfl_xor_sync(0xffffffffu, sq, off);
    }
    __shared__ float sh[16];
    int w = tid >> 5;
    if ((tid & 31) == 0) { sh[w] = s; sh[8 + w] = sq; }
    __syncthreads();
    s = 0.f; sq = 0.f;
#pragma unroll
    for (int i = 0; i < 8; i++) { s += sh[i]; sq += sh[8 + i]; }

    float mean = s * (1.f / 1024.f);
    float var  = fmaf(-mean, mean, sq * (1.f / 1024.f));
    float rstd = rsqrtf(var + 1e-6f);

    float4 g4 = *(const float4*)(g  + tid * 4);
    float4 b4 = *(const float4*)(be + tid * 4);
    float o[4];
    o[0] = (v[0] - mean) * rstd * g4.x + b4.x;
    o[1] = (v[1] - mean) * rstd * g4.y + b4.y;
    o[2] = (v[2] - mean) * rstd * g4.z + b4.z;
    o[3] = (v[3] - mean) * rstd * g4.w + b4.w;
    *(float4*)(out + base) = *(float4*)o;

    if (a2) {
        size_t ab = (size_t)row * GKA + tid * 4;
        __nv_bfloat16 h0, l0, h1, l1, h2, l2, h3, l3;
        split1(o[0], h0, l0); split1(o[1], h1, l1);
        split1(o[2], h2, l2); split1(o[3], h3, l3);
        uint2 hp = make_uint2(pack2(h0, h1), pack2(h2, h3));
        uint2 lp = make_uint2(pack2(l0, l1), pack2(l2, l3));
        *(uint2*)(a2 + ab)        = hp;
        *(uint2*)(a2 + ab + 1024) = lp;
    }
}

// ============================================================================
extern "C" void kernel_launch(void* const* d_in, const int* in_sizes, int n_in,
                              void* d_out, int out_size)
{
    const float* q    = (const float*)d_in[0];
    const float* k    = (const float*)d_in[1];
    const float* v    = (const float*)d_in[2];
    const int*   mask = (const int*)d_in[3];
    const float* Wq   = (const float*)d_in[4];
    const float* bq   = (const float*)d_in[5];
    const float* Wk   = (const float*)d_in[6];
    const float* bk   = (const float*)d_in[7];
    const float* Wv   = (const float*)d_in[8];
    const float* bv   = (const float*)d_in[9];
    const float* Wo   = (const float*)d_in[10];
    const float* bo   = (const float*)d_in[11];
    const float* g1   = (const float*)d_in[12];
    const float* b1   = (const float*)d_in[13];
    const float* g2   = (const float*)d_in[14];
    const float* b2   = (const float*)d_in[15];

    float *qp, *at, *x, *y, *mf;
    __nv_bfloat16 *aq, *ak, *av, *w2q, *w2k, *w2v, *w2o, *q2, *k2, *v2;
    cudaGetSymbolAddress((void**)&qp, g_qp);
    cudaGetSymbolAddress((void**)&at, g_att);
    cudaGetSymbolAddress((void**)&x,  g_x);
    cudaGetSymbolAddress((void**)&y,  g_y);
    cudaGetSymbolAddress((void**)&aq,  g_a2q);
    cudaGetSymbolAddress((void**)&ak,  g_a2k);
    cudaGetSymbolAddress((void**)&av,  g_a2v);
    cudaGetSymbolAddress((void**)&w2q, g_w2q);
    cudaGetSymbolAddress((void**)&w2k, g_w2k);
    cudaGetSymbolAddress((void**)&w2v, g_w2v);
    cudaGetSymbolAddress((void**)&w2o, g_w2o);
    cudaGetSymbolAddress((void**)&q2,  g_q2x);
    cudaGetSymbolAddress((void**)&k2,  g_k2x);
    cudaGetSymbolAddress((void**)&v2,  g_v2x);
    cudaGetSymbolAddress((void**)&mf,  g_mf);

    cudaFuncSetAttribute(gemm_qkv, cudaFuncAttributeMaxDynamicSharedMemorySize,
                         GEMM_SMEM);
    cudaFuncSetAttribute(gemm_o, cudaFuncAttributeMaxDynamicSharedMemorySize,
                         GEMM_SMEM);
    cudaFuncSetAttribute(flash_mma, cudaFuncAttributeMaxDynamicSharedMemorySize,
                         FLASH_SMEM);

    conv_w4<<<dim3(Dm / 32, Dm / 32, 4), dim3(32, 8)>>>(
        Wq, Wk, Wv, Wo, w2q, w2k, w2v, w2o);

    int cab4 = (int)(((size_t)NR * Dm) / 1024);
    conv_a3<<<dim3(cab4, 1, 3), 256>>>(q, k, v, aq, ak, av);
    conv_mask<<<(Bz * SKL + 255) / 256, 256>>>(mask, mf);

    gemm_qkv<<<dim3(Dm / 128, NR / 128, 3), 256, GEMM_SMEM>>>(
        aq, ak, av, w2q, w2k, w2v, bq, bk, bv, qp, q2, k2, v2);

    flash_mma<<<dim3(SQL / 128, Hh, Bz), 256, FLASH_SMEM>>>(q2, k2, v2, mf, at);

    add_ln<<<NR, 256>>>(qp, at, g1, b1, x, aq, 0);

    gemm_o<<<dim3(Dm / 128, NR / 128), 256, GEMM_SMEM>>>(aq, w2o, bo, y);

    add_ln<<<NR, 256>>>(x, y, g2, b2, (float*)d_out, (__nv_bfloat16*)0, 1);
}

// round 16
// speedup vs baseline: 1.2514x; 1.1126x over previous
#include <cuda_runtime.h>
#include <cuda_bf16.h>
#include <cstdint>
#include <math.h>

// Problem constants
#define Bz   4
#define SQL  2048
#define SKL  2048
#define Dm   1024
#define Hh   16
#define DHd  64
#define NR   (Bz*SQL)          // 8192 rows
#define GK   3072              // weight split K' = 3*1024
#define GKA  2048              // activation split storage (hi, lo)
#define NCHUNK 48              // 3-term chunk count
#define NCHUNK2 32             // 2-term chunk count (K, V projections)
#define HD2F 128               // flash Q split head dim 2*64

// -------- scratch (device globals; no allocation allowed) --------
__device__ float g_qp [NR*Dm];
__device__ float g_att[NR*Dm];
__device__ float g_x  [NR*Dm];
__device__ float g_y  [NR*Dm];
__device__ __nv_bfloat16 g_a2q[(size_t)NR*GKA];
__device__ __nv_bfloat16 g_a2k[(size_t)NR*GKA];
__device__ __nv_bfloat16 g_a2v[(size_t)NR*GKA];
__device__ __nv_bfloat16 g_w2q[(size_t)Dm*GK];
__device__ __nv_bfloat16 g_w2k[(size_t)Dm*GK];
__device__ __nv_bfloat16 g_w2v[(size_t)Dm*GK];
__device__ __nv_bfloat16 g_w2o[(size_t)Dm*GK];
__device__ __nv_bfloat16 g_q2x[(size_t)Bz*Hh*SQL*HD2F];
__device__ __nv_bfloat16 g_k2x[(size_t)Bz*Hh*SKL*DHd];
__device__ __nv_bfloat16 g_v2x[(size_t)Bz*Hh*SKL*DHd];
__device__ float g_mf [Bz*SKL];

// ============================================================================
// helpers
// ============================================================================
__device__ __forceinline__ uint32_t smem_u32(const void* p) {
    uint32_t a;
    asm("{ .reg .u64 t; cvta.to.shared.u64 t, %1; cvt.u32.u64 %0, t; }"
        : "=r"(a) : "l"(p));
    return a;
}
#define CP_ASYNC16(saddr, gptr) \
    asm volatile("cp.async.cg.shared.global [%0], [%1], 16;" \
                 :: "r"(saddr), "l"(gptr))
#define CP_COMMIT() asm volatile("cp.async.commit_group;" ::: "memory")
#define CP_WAIT1()  asm volatile("cp.async.wait_group 1;" ::: "memory")
#define CP_WAIT0()  asm volatile("cp.async.wait_group 0;" ::: "memory")

#define LDMX4(r0,r1,r2,r3,addr) \
    asm volatile("ldmatrix.sync.aligned.m8n8.x4.shared.b16 {%0,%1,%2,%3}, [%4];" \
                 : "=r"(r0), "=r"(r1), "=r"(r2), "=r"(r3) : "r"(addr))
#define LDMX4T(r0,r1,r2,r3,addr) \
    asm volatile("ldmatrix.sync.aligned.m8n8.x4.trans.shared.b16 {%0,%1,%2,%3}, [%4];" \
                 : "=r"(r0), "=r"(r1), "=r"(r2), "=r"(r3) : "r"(addr))

#define MMA16816(d, a, b) \
    asm volatile("mma.sync.aligned.m16n8k16.row.col.f32.bf16.bf16.f32 " \
                 "{%0,%1,%2,%3}, {%4,%5,%6,%7}, {%8,%9}, {%0,%1,%2,%3};" \
                 : "+f"((d)[0]), "+f"((d)[1]), "+f"((d)[2]), "+f"((d)[3]) \
                 : "r"((a)[0]), "r"((a)[1]), "r"((a)[2]), "r"((a)[3]), \
                   "r"((b)[0]), "r"((b)[1]))

__device__ __forceinline__ uint32_t packbf(float a, float b) {
    __nv_bfloat162 t = __floats2bfloat162_rn(a, b);
    return *(uint32_t*)&t;
}
__device__ __forceinline__ void split1(float v, __nv_bfloat16& hi, __nv_bfloat16& lo) {
    hi = __float2bfloat16(v);
    lo = __float2bfloat16(v - __bfloat162float(hi));
}
__device__ __forceinline__ uint32_t pack2(__nv_bfloat16 a, __nv_bfloat16 b) {
    return (uint32_t)(*(uint16_t*)&a) | ((uint32_t)(*(uint16_t*)&b) << 16);
}

// ============================================================================
// conversion kernels
// ============================================================================
// a2 layout: [hi(1024), lo(1024)] per row
__global__ __launch_bounds__(256) void conv_a3(
    const float* __restrict__ q, const float* __restrict__ k,
    const float* __restrict__ v,
    __nv_bfloat16* __restrict__ aq, __nv_bfloat16* __restrict__ ak,
    __nv_bfloat16* __restrict__ av)
{
    int z = blockIdx.z;
    const float* A = (z == 0) ? q : (z == 1) ? k : v;
    __nv_bfloat16* A2 = (z == 0) ? aq : (z == 1) ? ak : av;
    size_t i4 = (size_t)blockIdx.x * 256 + threadIdx.x;
    size_t e  = i4 * 4;
    int row = (int)(e >> 10);
    int kk  = (int)(e & 1023);
    float4 vv = *(const float4*)(A + e);
    __nv_bfloat16 h0, l0, h1, l1, h2, l2, h3, l3;
    split1(vv.x, h0, l0); split1(vv.y, h1, l1);
    split1(vv.z, h2, l2); split1(vv.w, h3, l3);
    uint2 hp = make_uint2(pack2(h0, h1), pack2(h2, h3));
    uint2 lp = make_uint2(pack2(l0, l1), pack2(l2, l3));
    size_t base = (size_t)row * GKA + kk;
    *(uint2*)(A2 + base)        = hp;
    *(uint2*)(A2 + base + 1024) = lp;
}

__global__ __launch_bounds__(256) void conv_w4(
    const float* __restrict__ Wq, const float* __restrict__ Wk,
    const float* __restrict__ Wv, const float* __restrict__ Wo,
    __nv_bfloat16* __restrict__ Tq, __nv_bfloat16* __restrict__ Tk,
    __nv_bfloat16* __restrict__ Tv, __nv_bfloat16* __restrict__ To)
{
    int z = blockIdx.z;
    const float* W = (z == 0) ? Wq : (z == 1) ? Wk : (z == 2) ? Wv : Wo;
    __nv_bfloat16* Wt = (z == 0) ? Tq : (z == 1) ? Tk : (z == 2) ? Tv : To;
    __shared__ float t[32][33];
    int tx = threadIdx.x, ty = threadIdx.y;
    int n0 = blockIdx.x * 32, k0 = blockIdx.y * 32;
#pragma unroll
    for (int i = 0; i < 4; i++)
        t[ty * 4 + i][tx] = W[(size_t)(k0 + ty * 4 + i) * Dm + n0 + tx];
    __syncthreads();
#pragma unroll
    for (int i = 0; i < 4; i++) {
        int n = ty * 4 + i;
        __nv_bfloat16 hi, lo;
        split1(t[tx][n], hi, lo);
        size_t base = (size_t)(n0 + n) * GK;
        Wt[base + k0 + tx]        = hi;
        Wt[base + 1024 + k0 + tx] = hi;
        Wt[base + 2048 + k0 + tx] = lo;
    }
}

__global__ __launch_bounds__(256) void conv_mask(
    const int* __restrict__ m, float* __restrict__ mf)
{
    int i = blockIdx.x * 256 + threadIdx.x;
    if (i < Bz * SKL) mf[i] = m[i] ? 1.0f : 0.0f;
}

// ============================================================================
// GEMM core: 128x128 tile, 64x32 warp tiles, 3-stage cp.async, 2 CTAs/SM
// nchunk = 48 (3-term) or 32 (2-term). A chunks c>=32 re-read hi (c-32).
// ============================================================================
#define SST   144
#define MATB  (128 * SST)
#define STAGEB (2 * MATB)          // 36864
#define GEMM_SMEM (3 * STAGEB)     // 110592

__device__ __forceinline__ void gemm_ld_chunk(
    const char* gA, const char* gB, uint32_t as, int tid, int c)
{
    uint32_t bs = as + MATB;
    int acb = ((c < 32) ? c : c - 32) * 128;
    int bcb = c * 128;
#pragma unroll
    for (int it = 0; it < 4; it++) {
        int f = tid + it * 256;
        int r = f >> 3, col = (f & 7) * 16;
        uint32_t so = (uint32_t)(r * SST + col);
        CP_ASYNC16(as + so, gA + (long)r * (GKA * 2) + acb + col);
        CP_ASYNC16(bs + so, gB + (long)r * (GK * 2) + bcb + col);
    }
    CP_COMMIT();
}

__device__ __forceinline__ void gemm_core(
    const char* gA, const char* gB, uint32_t sb, int tid,
    int warp_m, int warp_n, int lane, int nchunk, float acc[4][4][4])
{
#pragma unroll
    for (int mt = 0; mt < 4; mt++)
#pragma unroll
        for (int nt = 0; nt < 4; nt++)
#pragma unroll
            for (int r = 0; r < 4; r++) acc[mt][nt][r] = 0.f;

    gemm_ld_chunk(gA, gB, sb, tid, 0);
    gemm_ld_chunk(gA, gB, sb + STAGEB, tid, 1);

    int arow = warp_m * 64 + (lane & 15);
    int acol = ((lane >> 4) << 3);
    int brow = warp_n * 32 + (lane & 7) + ((lane >> 4) << 3);
    int bcol = (((lane >> 3) & 1) << 3);

    for (int c = 0; c < nchunk; c++) {
        if (c < nchunk - 1) { CP_WAIT1(); } else { CP_WAIT0(); }
        __syncthreads();
        if (c + 2 < nchunk)
            gemm_ld_chunk(gA, gB, sb + ((c + 2) % 3) * STAGEB, tid, c + 2);

        uint32_t aS = sb + (c % 3) * STAGEB;
        uint32_t bS = aS + MATB;

#pragma unroll
        for (int ks = 0; ks < 4; ks++) {
            uint32_t a[4][4];
            uint32_t b[4][2];
#pragma unroll
            for (int mt = 0; mt < 4; mt++) {
                uint32_t ad = aS + (uint32_t)((arow + mt * 16) * SST
                                              + (ks * 16 + acol) * 2);
                LDMX4(a[mt][0], a[mt][1], a[mt][2], a[mt][3], ad);
            }
#pragma unroll
            for (int nh = 0; nh < 2; nh++) {
                uint32_t bd = bS + (uint32_t)((brow + nh * 16) * SST
                                              + (ks * 16 + bcol) * 2);
                LDMX4(b[nh * 2][0], b[nh * 2][1],
                      b[nh * 2 + 1][0], b[nh * 2 + 1][1], bd);
            }
#pragma unroll
            for (int mt = 0; mt < 4; mt++)
#pragma unroll
                for (int nt = 0; nt < 4; nt++)
                    MMA16816(acc[mt][nt], a[mt], b[nt]);
        }
    }
}

// Batched QKV projection GEMM. z=0: Q, 3-term, qp fp32 + q2[qh,ql];
// z=1: K, 2-term, k2; z=2: V, 2-term, v2.
__global__ __launch_bounds__(256) void gemm_qkv(
    const __nv_bfloat16* __restrict__ aq, const __nv_bfloat16* __restrict__ ak,
    const __nv_bfloat16* __restrict__ av,
    const __nv_bfloat16* __restrict__ wq, const __nv_bfloat16* __restrict__ wk,
    const __nv_bfloat16* __restrict__ wv,
    const float* __restrict__ bq, const float* __restrict__ bk,
    const float* __restrict__ bv,
    float* __restrict__ qp, __nv_bfloat16* __restrict__ q2,
    __nv_bfloat16* __restrict__ k2, __nv_bfloat16* __restrict__ v2)
{
    extern __shared__ char smem[];
    uint32_t sb = smem_u32(smem);
    int tid  = threadIdx.x;
    int wid  = tid >> 5;
    int lane = tid & 31;
    int bx = blockIdx.x, by = blockIdx.y, z = blockIdx.z;
    int warp_m = wid >> 2, warp_n = wid & 3;

    const __nv_bfloat16* A2 = (z == 0) ? aq : (z == 1) ? ak : av;
    const __nv_bfloat16* B2 = (z == 0) ? wq : (z == 1) ? wk : wv;
    const float* bias       = (z == 0) ? bq : (z == 1) ? bk : bv;
    int nchunk              = (z == 0) ? NCHUNK : NCHUNK2;

    float acc[4][4][4];
    gemm_core((const char*)(A2 + (size_t)(by * 128) * GKA),
              (const char*)(B2 + (size_t)(bx * 128) * GK),
              sb, tid, warp_m, warp_n, lane, nchunk, acc);

    int g  = lane >> 2;
    int tg = lane & 3;
#pragma unroll
    for (int mt = 0; mt < 4; mt++) {
        int row0 = by * 128 + warp_m * 64 + mt * 16 + g;
#pragma unroll
        for (int nt = 0; nt < 4; nt++) {
            int col = bx * 128 + warp_n * 32 + nt * 8 + tg * 2;
            float2 bv2 = *(const float2*)(bias + col);
            int h = col >> 6, d = col & 63;
#pragma unroll
            for (int half = 0; half < 2; half++) {
                int row = row0 + half * 8;
                float v0 = acc[mt][nt][2 * half]     + bv2.x;
                float v1 = acc[mt][nt][2 * half + 1] + bv2.y;
                int bb = row >> 11, r = row & 2047;
                size_t hb = (size_t)((bb * 16 + h) * 2048 + r);
                __nv_bfloat16 h0, l0, h1, l1;
                split1(v0, h0, l0);
                split1(v1, h1, l1);
                uint32_t hp = pack2(h0, h1);
                uint32_t lp = pack2(l0, l1);
                if (z == 0) {
                    float2 o = {v0, v1};
                    *(float2*)(qp + (size_t)row * Dm + col) = o;
                    size_t base = hb * HD2F;
                    *(uint32_t*)(q2 + base + d)      = hp;   // qh
                    *(uint32_t*)(q2 + base + 64 + d) = lp;   // ql
                } else if (z == 1) {
                    *(uint32_t*)(k2 + hb * DHd + d) = hp;    // kh
                } else {
                    *(uint32_t*)(v2 + hb * DHd + d) = hp;
                }
            }
        }
    }
}

// Output projection GEMM (3-term)
__global__ __launch_bounds__(256) void gemm_o(
    const __nv_bfloat16* __restrict__ A2, const __nv_bfloat16* __restrict__ B2,
    const float* __restrict__ bias, float* __restrict__ C)
{
    extern __shared__ char smem[];
    uint32_t sb = smem_u32(smem);
    int tid  = threadIdx.x;
    int wid  = tid >> 5;
    int lane = tid & 31;
    int bx = blockIdx.x, by = blockIdx.y;
    int warp_m = wid >> 2, warp_n = wid & 3;

    float acc[4][4][4];
    gemm_core((const char*)(A2 + (size_t)(by * 128) * GKA),
              (const char*)(B2 + (size_t)(bx * 128) * GK),
              sb, tid, warp_m, warp_n, lane, NCHUNK, acc);

    int g  = lane >> 2;
    int tg = lane & 3;
#pragma unroll
    for (int mt = 0; mt < 4; mt++) {
        int row = by * 128 + warp_m * 64 + mt * 16 + g;
#pragma unroll
        for (int nt = 0; nt < 4; nt++) {
            int col = bx * 128 + warp_n * 32 + nt * 8 + tg * 2;
            float2 bv = *(const float2*)(bias + col);
            float2 o0 = {acc[mt][nt][0] + bv.x, acc[mt][nt][1] + bv.y};
            float2 o1 = {acc[mt][nt][2] + bv.x, acc[mt][nt][3] + bv.y};
            *(float2*)(C + (size_t)row * Dm + col)       = o0;
            *(float2*)(C + (size_t)(row + 8) * Dm + col) = o1;
        }
    }
}

// ============================================================================
// Flash attention: Q split [qh,ql] vs single-copy K (same K frags reused)
// ============================================================================
#define QROWB 272
#define KROWB 144
#define VROWB 144
#define KTILEB (64 * KROWB)        // 9216
#define VOFF   KTILEB
#define MOFF   (KTILEB + 64 * VROWB)   // 18432
#define STGB   (MOFF + 256)        // 18688
#define FLASH_SMEM (3 * STGB)      // 56064

__device__ __forceinline__ void flash_prefetch(
    uint32_t ds, const char* gK, const char* gV, const char* gM,
    int kt, int tid)
{
    const char* nK = gK + (long)kt * 64 * 128;
    const char* nV = gV + (long)kt * 64 * 128;
#pragma unroll
    for (int it = 0; it < 2; it++) {
        int f = tid + it * 256;
        int r = f >> 3, c = f & 7;
        CP_ASYNC16(ds + r * KROWB + c * 16, nK + (long)r * 128 + c * 16);
    }
#pragma unroll
    for (int it = 0; it < 2; it++) {
        int f = tid + it * 256;
        int r = f >> 3, c = f & 7;
        CP_ASYNC16(ds + VOFF + r * VROWB + c * 16, nV + (long)r * 128 + c * 16);
    }
    if (tid < 16) CP_ASYNC16(ds + MOFF + tid * 16, gM + kt * 256 + tid * 16);
    CP_COMMIT();
}

__global__ __launch_bounds__(256, 1) void flash_mma(
    const __nv_bfloat16* __restrict__ Q2, const __nv_bfloat16* __restrict__ K2,
    const __nv_bfloat16* __restrict__ V2, const float* __restrict__ MF,
    float* __restrict__ attn)
{
    extern __shared__ char smem[];
    uint32_t sb = smem_u32(smem);
    int tid  = threadIdx.x;
    int wid  = tid >> 5;
    int lane = tid & 31;
    int qx = blockIdx.x, h = blockIdx.y, b = blockIdx.z;

    size_t bh = (size_t)(b * 16 + h) * 2048;
    const char* gQ = (const char*)(Q2 + (bh + qx * 128) * HD2F);
    const char* gK = (const char*)(K2 + bh * DHd);
    const char* gV = (const char*)(V2 + bh * DHd);
    const char* gM = (const char*)(MF + b * SKL);

#pragma unroll
    for (int it = 0; it < 8; it++) {
        int f = tid + it * 256;
        int r = f >> 4, c = f & 15;
        CP_ASYNC16(sb + r * QROWB + c * 16, gQ + (long)r * (HD2F * 2) + c * 16);
    }
    CP_COMMIT();
    CP_WAIT0();
    __syncthreads();

    uint32_t qf[8][4];           // ks 0..3 = qh, ks 4..7 = ql
    {
        int arow = wid * 16 + (lane & 15);
        int acol = ((lane >> 4) << 3);
#pragma unroll
        for (int ks = 0; ks < 8; ks++)
            LDMX4(qf[ks][0], qf[ks][1], qf[ks][2], qf[ks][3],
                  sb + arow * QROWB + (ks * 16 + acol) * 2);
    }
    __syncthreads();

    int g  = lane >> 2;
    int tg = lane & 3;

    float O[8][4];
#pragma unroll
    for (int dt = 0; dt < 8; dt++)
#pragma unroll
        for (int r = 0; r < 4; r++) O[dt][r] = 0.f;
    float m0 = -30000.f, m1 = -30000.f, l0 = 0.f, l1 = 0.f;

    const float scale = 0.03125f;

    flash_prefetch(sb,        gK, gV, gM, 0, tid);
    flash_prefetch(sb + STGB, gK, gV, gM, 1, tid);

    int brow = (lane & 7) + ((lane >> 4) << 3);
    int bcol = (((lane >> 3) & 1) << 3);
    int vrow = (lane & 7) + (((lane >> 3) & 1) << 3);
    int vcol = ((lane >> 4) << 3);

    for (int kt = 0; kt < 32; kt++) {
        if (kt < 31) { CP_WAIT1(); } else { CP_WAIT0(); }
        __syncthreads();
        if (kt + 2 < 32)
            flash_prefetch(sb + ((kt + 2) % 3) * STGB, gK, gV, gM, kt + 2, tid);

        uint32_t kS = sb + (kt % 3) * STGB;
        uint32_t vS = kS + VOFF;
        uint32_t mS = kS + MOFF;

        // ---- S = qh K^T + ql K^T (same K fragments) ----
        float s[8][4];
#pragma unroll
        for (int nt = 0; nt < 8; nt++)
#pragma unroll
            for (int r = 0; r < 4; r++) s[nt][r] = 0.f;

#pragma unroll
        for (int idx = 0; idx < 16; idx++) {
            int ks = idx >> 2, j = idx & 3;
            uint32_t kb[2][2];
            LDMX4(kb[0][0], kb[0][1], kb[1][0], kb[1][1],
                  kS + (uint32_t)((j * 16 + brow) * KROWB
                                  + (ks * 16 + bcol) * 2));
            MMA16816(s[2 * j],     qf[ks],     kb[0]);
            MMA16816(s[2 * j + 1], qf[ks],     kb[1]);
            MMA16816(s[2 * j],     qf[ks + 4], kb[0]);
            MMA16816(s[2 * j + 1], qf[ks + 4], kb[1]);
        }

        // ---- softmax (online) ----
        float mf[8][2];
#pragma unroll
        for (int nt = 0; nt < 8; nt++) {
            mf[nt][0] = *(const float*)((const char*)smem + (mS - sb) + (nt * 8 + 2 * tg) * 4);
            mf[nt][1] = *(const float*)((const char*)smem + (mS - sb) + (nt * 8 + 2 * tg + 1) * 4);
        }
        float rm0 = -30000.f, rm1 = -30000.f;
#pragma unroll
        for (int nt = 0; nt < 8; nt++) {
#pragma unroll
            for (int e = 0; e < 2; e++) {
                float off = (mf[nt][e] - 1.0f) * 30000.f;
                s[nt][e]     = s[nt][e]     * scale + off;
                s[nt][2 + e] = s[nt][2 + e] * scale + off;
                rm0 = fmaxf(rm0, s[nt][e]);
                rm1 = fmaxf(rm1, s[nt][2 + e]);
            }
        }
        rm0 = fmaxf(rm0, __shfl_xor_sync(0xffffffffu, rm0, 1));
        rm0 = fmaxf(rm0, __shfl_xor_sync(0xffffffffu, rm0, 2));
        rm1 = fmaxf(rm1, __shfl_xor_sync(0xffffffffu, rm1, 1));
        rm1 = fmaxf(rm1, __shfl_xor_sync(0xffffffffu, rm1, 2));

        float mn0 = fmaxf(m0, rm0), mn1 = fmaxf(m1, rm1);
        float al0 = __expf(m0 - mn0), al1 = __expf(m1 - mn1);
        m0 = mn0; m1 = mn1;

        float rs0 = 0.f, rs1 = 0.f;
#pragma unroll
        for (int nt = 0; nt < 8; nt++) {
#pragma unroll
            for (int e = 0; e < 2; e++) {
                float p0 = __expf(s[nt][e]     - mn0) * mf[nt][e];
                float p1 = __expf(s[nt][2 + e] - mn1) * mf[nt][e];
                s[nt][e] = p0;  s[nt][2 + e] = p1;
                rs0 += p0;  rs1 += p1;
            }
        }
        rs0 += __shfl_xor_sync(0xffffffffu, rs0, 1);
        rs0 += __shfl_xor_sync(0xffffffffu, rs0, 2);
        rs1 += __shfl_xor_sync(0xffffffffu, rs1, 1);
        rs1 += __shfl_xor_sync(0xffffffffu, rs1, 2);
        l0 = l0 * al0 + rs0;
        l1 = l1 * al1 + rs1;

#pragma unroll
        for (int dt = 0; dt < 8; dt++) {
            O[dt][0] *= al0; O[dt][1] *= al0;
            O[dt][2] *= al1; O[dt][3] *= al1;
        }

        // ---- O += P V ----
        uint32_t pa[4][4];
#pragma unroll
        for (int ks = 0; ks < 4; ks++) {
            pa[ks][0] = packbf(s[2 * ks][0],     s[2 * ks][1]);
            pa[ks][1] = packbf(s[2 * ks][2],     s[2 * ks][3]);
            pa[ks][2] = packbf(s[2 * ks + 1][0], s[2 * ks + 1][1]);
            pa[ks][3] = packbf(s[2 * ks + 1][2], s[2 * ks + 1][3]);
        }
#pragma unroll
        for (int idx = 0; idx < 16; idx++) {
            int ks = idx >> 2, j = idx & 3;
            uint32_t vb[2][2];
            LDMX4T(vb[0][0], vb[0][1], vb[1][0], vb[1][1],
                   vS + (uint32_t)((ks * 16 + vrow) * VROWB
                                   + (j * 16 + vcol) * 2));
            MMA16816(O[2 * j],     pa[ks], vb[0]);
            MMA16816(O[2 * j + 1], pa[ks], vb[1]);
        }
    }

    float inv0 = l0 > 0.f ? 1.f / l0 : 0.f;
    float inv1 = l1 > 0.f ? 1.f / l1 : 0.f;
    int row0 = qx * 128 + wid * 16 + g;
    float* oBase = attn + (size_t)(b * SQL) * Dm + h * DHd;
#pragma unroll
    for (int dt = 0; dt < 8; dt++) {
        int col = dt * 8 + 2 * tg;
        float2 o0 = {O[dt][0] * inv0, O[dt][1] * inv0};
        float2 o1 = {O[dt][2] * inv1, O[dt][3] * inv1};
        *(float2*)(oBase + (size_t)row0 * Dm + col)       = o0;
        *(float2*)(oBase + (size_t)(row0 + 8) * Dm + col) = o1;
    }
}

// ============================================================================
// out = LayerNorm(X + (relu? relu(Y) : Y)) * g + beta; optional split output
// ============================================================================
__global__ __launch_bounds__(256) void add_ln(
    const float* __restrict__ X, const float* __restrict__ Y,
    const float* __restrict__ g, const float* __restrict__ be,
    float* __restrict__ out, __nv_bfloat16* __restrict__ a2, int dorelu)
{
    int row = blockIdx.x;
    int tid = threadIdx.x;
    size_t base = (size_t)row * Dm + tid * 4;

    float4 x4 = *(const float4*)(X + base);
    float4 y4 = *(const float4*)(Y + base);
    if (dorelu) {
        y4.x = fmaxf(y4.x, 0.f); y4.y = fmaxf(y4.y, 0.f);
        y4.z = fmaxf(y4.z, 0.f); y4.w = fmaxf(y4.w, 0.f);
    }
    float v[4] = {x4.x + y4.x, x4.y + y4.y, x4.z + y4.z, x4.w + y4.w};

    float s  = v[0] + v[1] + v[2] + v[3];
    float sq = v[0]*v[0] + v[1]*v[1] + v[2]*v[2] + v[3]*v[3];
#pragma unroll
    for (int off = 16; off > 0; off >>= 1) {
        s  += __shfl_xor_sync(0xffffffffu, s,  off);
        sq += __shfl_xor_sync(0xffffffffu, sq, off);
    }
    __shared__ float sh[16];
    int w = tid >> 5;
    if ((tid & 31) == 0) { sh[w] = s; sh[8 + w] = sq; }
    __syncthreads();
    s = 0.f; sq = 0.f;
#pragma unroll
    for (int i = 0; i < 8; i++) { s += sh[i]; sq += sh[8 + i]; }

    float mean = s * (1.f / 1024.f);
    float var  = fmaf(-mean, mean, sq * (1.f / 1024.f));
    float rstd = rsqrtf(var + 1e-6f);

    float4 g4 = *(const float4*)(g  + tid * 4);
    float4 b4 = *(const float4*)(be + tid * 4);
    float o[4];
    o[0] = (v[0] - mean) * rstd * g4.x + b4.x;
    o[1] = (v[1] - mean) * rstd * g4.y + b4.y;
    o[2] = (v[2] - mean) * rstd * g4.z + b4.z;
    o[3] = (v[3] - mean) * rstd * g4.w + b4.w;
    *(float4*)(out + base) = *(float4*)o;

    if (a2) {
        size_t ab = (size_t)row * GKA + tid * 4;
        __nv_bfloat16 h0, l0, h1, l1, h2, l2, h3, l3;
        split1(o[0], h0, l0); split1(o[1], h1, l1);
        split1(o[2], h2, l2); split1(o[3], h3, l3);
        uint2 hp = make_uint2(pack2(h0, h1), pack2(h2, h3));
        uint2 lp = make_uint2(pack2(l0, l1), pack2(l2, l3));
        *(uint2*)(a2 + ab)        = hp;
        *(uint2*)(a2 + ab + 1024) = lp;
    }
}

// ============================================================================
extern "C" void kernel_launch(void* const* d_in, const int* in_sizes, int n_in,
                              void* d_out, int out_size)
{
    const float* q    = (const float*)d_in[0];
    const float* k    = (const float*)d_in[1];
    const float* v    = (const float*)d_in[2];
    const int*   mask = (const int*)d_in[3];
    const float* Wq   = (const float*)d_in[4];
    const float* bq   = (const float*)d_in[5];
    const float* Wk   = (const float*)d_in[6];
    const float* bk   = (const float*)d_in[7];
    const float* Wv   = (const float*)d_in[8];
    const float* bv   = (const float*)d_in[9];
    const float* Wo   = (const float*)d_in[10];
    const float* bo   = (const float*)d_in[11];
    const float* g1   = (const float*)d_in[12];
    const float* b1   = (const float*)d_in[13];
    const float* g2   = (const float*)d_in[14];
    const float* b2   = (const float*)d_in[15];

    float *qp, *at, *x, *y, *mf;
    __nv_bfloat16 *aq, *ak, *av, *w2q, *w2k, *w2v, *w2o, *q2, *k2, *v2;
    cudaGetSymbolAddress((void**)&qp, g_qp);
    cudaGetSymbolAddress((void**)&at, g_att);
    cudaGetSymbolAddress((void**)&x,  g_x);
    cudaGetSymbolAddress((void**)&y,  g_y);
    cudaGetSymbolAddress((void**)&aq,  g_a2q);
    cudaGetSymbolAddress((void**)&ak,  g_a2k);
    cudaGetSymbolAddress((void**)&av,  g_a2v);
    cudaGetSymbolAddress((void**)&w2q, g_w2q);
    cudaGetSymbolAddress((void**)&w2k, g_w2k);
    cudaGetSymbolAddress((void**)&w2v, g_w2v);
    cudaGetSymbolAddress((void**)&w2o, g_w2o);
    cudaGetSymbolAddress((void**)&q2,  g_q2x);
    cudaGetSymbolAddress((void**)&k2,  g_k2x);
    cudaGetSymbolAddress((void**)&v2,  g_v2x);
    cudaGetSymbolAddress((void**)&mf,  g_mf);

    cudaFuncSetAttribute(gemm_qkv, cudaFuncAttributeMaxDynamicSharedMemorySize,
                         GEMM_SMEM);
    cudaFuncSetAttribute(gemm_o, cudaFuncAttributeMaxDynamicSharedMemorySize,
                         GEMM_SMEM);
    cudaFuncSetAttribute(flash_mma, cudaFuncAttributeMaxDynamicSharedMemorySize,
                         FLASH_SMEM);

    conv_w4<<<dim3(Dm / 32, Dm / 32, 4), dim3(32, 8)>>>(
        Wq, Wk, Wv, Wo, w2q, w2k, w2v, w2o);

    int cab4 = (int)(((size_t)NR * Dm) / 1024);
    conv_a3<<<dim3(cab4, 1, 3), 256>>>(q, k, v, aq, ak, av);
    conv_mask<<<(Bz * SKL + 255) / 256, 256>>>(mask, mf);

    gemm_qkv<<<dim3(Dm / 128, NR / 128, 3), 256, GEMM_SMEM>>>(
        aq, ak, av, w2q, w2k, w2v, bq, bk, bv, qp, q2, k2, v2);

    flash_mma<<<dim3(SQL / 128, Hh, Bz), 256, FLASH_SMEM>>>(q2, k2, v2, mf, at);

    add_ln<<<NR, 256>>>(qp, at, g1, b1, x, aq, 0);

    gemm_o<<<dim3(Dm / 128, NR / 128), 256, GEMM_SMEM>>>(aq, w2o, bo, y);

    add_ln<<<NR, 256>>>(x, y, g2, b2, (float*)d_out, (__nv_bfloat16*)0, 1);
}